// round 14
// baseline (speedup 1.0000x reference)
#include <cuda_runtime.h>
#include <cuda_fp16.h>
#include <cstdint>

#define C_DIM   256
#define MAXN    100000
#define EPS_LN  1e-5f

typedef __half f16;

// ---------------- device scratch ----------------
__device__ float g_agg  [MAXN * C_DIM];   // zero-init at module load; norm_agg re-zeros
__device__ float g_new_u[MAXN * C_DIM];
__device__ float g_new_i[MAXN * C_DIM];
__device__ float g_cnt_i[MAXN];
__device__ float g_cnt_u[MAXN];

__device__ __align__(16) f16 g_xu_f[MAXN * C_DIM];
__device__ __align__(16) f16 g_xi_f[MAXN * C_DIM];
__device__ __align__(16) f16 g_h_f [MAXN * C_DIM];
__device__ __align__(16) f16 g_a_f [MAXN * C_DIM];
__device__ __align__(16) f16 g_p_f [MAXN * C_DIM];

// per conv: W1T | WxT | W2T | WaT, each [256,256] K-major [n,k]
#define WSTRIDE (262144)
__device__ __align__(16) f16 g_w[4 * WSTRIDE];

// ---------------- helpers ----------------
__device__ __forceinline__ uint32_t smem_u32(const void* p) {
    uint32_t a;
    asm("{ .reg .u64 t; cvta.to.shared.u64 t, %1; cvt.u32.u64 %0, t; }" : "=r"(a) : "l"(p));
    return a;
}
__device__ __forceinline__ void cp16(uint32_t s, const void* g) {
    asm volatile("cp.async.cg.shared.global [%0], [%1], 16;" :: "r"(s), "l"(g));
}
__device__ __forceinline__ void cp_commit() { asm volatile("cp.async.commit_group;" ::: "memory"); }
template<int N> __device__ __forceinline__ void cp_wait() {
    asm volatile("cp.async.wait_group %0;" :: "n"(N) : "memory");
}
#define SW128(o) ((o) ^ (((o) >> 3) & 0x70))

__device__ __forceinline__ uint32_t pack_h2(float a, float b) {
    __half2 t = __halves2half2(__float2half_rn(a), __float2half_rn(b));
    return *reinterpret_cast<uint32_t*>(&t);
}

#define LDSM4(r0, r1, r2, r3, addr) \
    asm volatile("ldmatrix.sync.aligned.m8n8.x4.shared.b16 {%0,%1,%2,%3}, [%4];" \
                 : "=r"(r0), "=r"(r1), "=r"(r2), "=r"(r3) : "r"(addr))

#define MMA16816F(d, a, b0, b1) \
    asm volatile("mma.sync.aligned.m16n8k16.row.col.f32.f16.f16.f32 " \
                 "{%0,%1,%2,%3}, {%4,%5,%6,%7}, {%8,%9}, {%0,%1,%2,%3};" \
                 : "+f"((d)[0]), "+f"((d)[1]), "+f"((d)[2]), "+f"((d)[3]) \
                 : "r"((a)[0]), "r"((a)[1]), "r"((a)[2]), "r"((a)[3]), \
                   "r"(b0), "r"(b1))

__device__ __forceinline__ float warp_sum(float v) {
#pragma unroll
    for (int o = 16; o > 0; o >>= 1) v += __shfl_xor_sync(0xffffffffu, v, o);
    return v;
}

// ---------------- warp-MMA GEMM (single-term fp16) ----------------
// out[M, *] = A[M,256] @ B^T; A,B fp16 (B K-major [n,256]).
// Block tile 128(M) x 128(N), 256 threads, 8 warps (2m x 4n), warp tile 64x32.
// EPI 0: outH = f16(D + bias1)                            (P)
// EPI 1: outF += D                                        (new += agg@Wa)
// EPI 3: cols<256 -> outH = f16(relu(D+bias1)); cols>=256 -> outF = D + bias2
#define CHUNK_BYTES 32768
#define GEMM_SMEM   (2 * CHUNK_BYTES)

__device__ __forceinline__ void gemm_load_chunk(
    uint32_t sbuf, int tid, int m0, int n0, int M, int c,
    const f16* Af, const f16* Bf)
{
    const int k0 = c * 64;
#pragma unroll
    for (int i = 0; i < 4; i++) {              // A: 128 rows x 128B
        int idx = tid + i * 256;
        int r = idx >> 3, u = idx & 7;
        int rg = min(m0 + r, M - 1);
        uint32_t so = SW128((uint32_t)(r * 128 + u * 16));
        cp16(sbuf + so, (const char*)(Af + (size_t)rg * C_DIM + k0) + u * 16);
    }
#pragma unroll
    for (int i = 0; i < 4; i++) {              // B: 128 n-rows x 128B
        int idx = tid + i * 256;
        int r = idx >> 3, u = idx & 7;
        uint32_t so = SW128((uint32_t)(r * 128 + u * 16));
        cp16(sbuf + 16384 + so, (const char*)(Bf + (size_t)(n0 + r) * C_DIM + k0) + u * 16);
    }
}

template<int EPI>
__global__ __launch_bounds__(256, 2)
void gemm_mma(const f16* __restrict__ Af, const f16* __restrict__ Bf,
              const float* __restrict__ bias1, const float* __restrict__ bias2,
              float* __restrict__ outF, f16* __restrict__ outH, int M)
{
    extern __shared__ char smem[];
    const uint32_t sb = smem_u32(smem);
    const int tid  = threadIdx.x;
    const int lane = tid & 31;
    const int wid  = tid >> 5;
    const int wm   = wid >> 2;
    const int wn   = wid & 3;
    const int m0   = blockIdx.x * 128;
    const int n0   = blockIdx.y * 128;

    const uint32_t aOff = (uint32_t)((wm * 64 + (lane & 15)) * 128 + ((lane >> 4) << 4));
    const uint32_t bOff = (uint32_t)((wn * 32 + (lane & 7) + ((lane >> 4) << 3)) * 128
                                     + (((lane >> 3) & 1) << 4));

    float D[4][4][4];
#pragma unroll
    for (int g = 0; g < 4; g++)
#pragma unroll
        for (int n = 0; n < 4; n++)
#pragma unroll
            for (int q = 0; q < 4; q++) D[g][n][q] = 0.f;

    gemm_load_chunk(sb, tid, m0, n0, M, 0, Af, Bf);
    cp_commit();

#pragma unroll
    for (int c = 0; c < 4; c++) {
        if (c + 1 < 4) {
            gemm_load_chunk(sb + (uint32_t)((c + 1) & 1) * CHUNK_BYTES,
                            tid, m0, n0, M, c + 1, Af, Bf);
            cp_commit();
            cp_wait<1>();
        } else {
            cp_wait<0>();
        }
        __syncthreads();

        const uint32_t base = sb + (uint32_t)(c & 1) * CHUNK_BYTES;
#pragma unroll
        for (int ks = 0; ks < 4; ks++) {
            const uint32_t kb = (uint32_t)(ks * 32);
            uint32_t af[4][4];
#pragma unroll
            for (int g = 0; g < 4; g++) {
                uint32_t sw = SW128(aOff + (uint32_t)(g * 2048) + kb);
                LDSM4(af[g][0], af[g][1], af[g][2], af[g][3], base + sw);
            }
            uint32_t bh[2][4];
#pragma unroll
            for (int p = 0; p < 2; p++) {
                uint32_t sw = SW128(bOff + (uint32_t)(p * 2048) + kb);
                LDSM4(bh[p][0], bh[p][1], bh[p][2], bh[p][3], base + 16384 + sw);
            }
#pragma unroll
            for (int g = 0; g < 4; g++) {
#pragma unroll
                for (int n = 0; n < 4; n++) {
                    const int p = n >> 1, rb = (n & 1) * 2;
                    MMA16816F(D[g][n], af[g], bh[p][rb], bh[p][rb + 1]);
                }
            }
        }
        __syncthreads();
    }

    // ---- epilogue ----
#pragma unroll
    for (int g = 0; g < 4; g++) {
#pragma unroll
        for (int n = 0; n < 4; n++) {
            int r0  = m0 + wm * 64 + g * 16 + (lane >> 2);
            int col = n0 + wn * 32 + n * 8 + (lane & 3) * 2;
            if (EPI == 0) {
                float2 bv = *(const float2*)(bias1 + col);
                if (r0 < M)
                    *(uint32_t*)(outH + (size_t)r0 * C_DIM + col) =
                        pack_h2(D[g][n][0] + bv.x, D[g][n][1] + bv.y);
                if (r0 + 8 < M)
                    *(uint32_t*)(outH + (size_t)(r0 + 8) * C_DIM + col) =
                        pack_h2(D[g][n][2] + bv.x, D[g][n][3] + bv.y);
            } else if (EPI == 1) {
                if (r0 < M) {
                    float2* p = (float2*)(outF + (size_t)r0 * C_DIM + col);
                    float2 o = *p;
                    *p = make_float2(o.x + D[g][n][0], o.y + D[g][n][1]);
                }
                if (r0 + 8 < M) {
                    float2* p = (float2*)(outF + (size_t)(r0 + 8) * C_DIM + col);
                    float2 o = *p;
                    *p = make_float2(o.x + D[g][n][2], o.y + D[g][n][3]);
                }
            } else {  // EPI 3
                if (col < 256) {
                    float2 bv = *(const float2*)(bias1 + col);
                    if (r0 < M)
                        *(uint32_t*)(outH + (size_t)r0 * C_DIM + col) =
                            pack_h2(fmaxf(D[g][n][0] + bv.x, 0.f),
                                    fmaxf(D[g][n][1] + bv.y, 0.f));
                    if (r0 + 8 < M)
                        *(uint32_t*)(outH + (size_t)(r0 + 8) * C_DIM + col) =
                            pack_h2(fmaxf(D[g][n][2] + bv.x, 0.f),
                                    fmaxf(D[g][n][3] + bv.y, 0.f));
                } else {
                    int cf = col - 256;
                    float2 bv = *(const float2*)(bias2 + cf);
                    if (r0 < M)
                        *(float2*)(outF + (size_t)r0 * C_DIM + cf) =
                            make_float2(D[g][n][0] + bv.x, D[g][n][1] + bv.y);
                    if (r0 + 8 < M)
                        *(float2*)(outF + (size_t)(r0 + 8) * C_DIM + cf) =
                            make_float2(D[g][n][2] + bv.x, D[g][n][3] + bv.y);
                }
            }
        }
    }
}

// ---------------- aux kernels ----------------
__global__ void f32_to_f16_kernel(const float* __restrict__ x,
                                  f16* __restrict__ out, int n4)
{
    int idx = blockIdx.x * blockDim.x + threadIdx.x;
    if (idx >= n4) return;
    float4 v = ((const float4*)x)[idx];
    *(uint2*)(out + (size_t)idx * 4) = make_uint2(pack_h2(v.x, v.y), pack_h2(v.z, v.w));
}

// One launch converts ALL weights for all 4 convs into g_w (transposed fp16).
// Layout per conv t: W1T | WxT | W2T | WaT (each 65536 elems).
__global__ void convert_all_w_kernel(const float* __restrict__ pw1,
                                     const float* __restrict__ pw2,
                                     const float* __restrict__ lin_w,
                                     f16* __restrict__ out)
{
    int idx = blockIdx.x * blockDim.x + threadIdx.x;
    if (idx >= 4 * WSTRIDE) return;
    int t   = idx >> 18;            // / 262144
    int rem = idx & (WSTRIDE - 1);
    int m   = rem >> 16;            // 0..3
    int e   = rem & 65535;
    int n   = e >> 8, k = e & 255;
    float v;
    if (m == 0)      v = pw1[(size_t)t * 65536 + k * 256 + n];
    else if (m == 1) v = lin_w[(size_t)t * 131072 + k * 256 + n];
    else if (m == 2) v = pw2[(size_t)t * 65536 + k * 256 + n];
    else             v = lin_w[(size_t)t * 131072 + 65536 + k * 256 + n];
    out[idx] = __float2half_rn(v);
}

__global__ void count_kernel(const int* __restrict__ dst, float* __restrict__ cnt, int nE)
{
    int i = blockIdx.x * blockDim.x + threadIdx.x;
    if (i < nE) atomicAdd(cnt + __ldg(dst + i), 1.0f);
}

// fp16 edge stage: msg = LN(x_src[s] - P[d]) * g + b, red into fp32 agg
__global__ void edge_msg_kernel(const f16* __restrict__ xsrc,
                                const f16* __restrict__ Pn,
                                const int* __restrict__ ei,
                                const float* __restrict__ gg,
                                const float* __restrict__ bb,
                                float* __restrict__ agg, int nE)
{
    int w = (blockIdx.x * blockDim.x + threadIdx.x) >> 5;
    int lane = threadIdx.x & 31;
    if (w >= nE) return;
    int s = __ldg(ei + w);
    int d = __ldg(ei + nE + w);
    int c0 = lane << 3;

    uint4 xv = *(const uint4*)(xsrc + (size_t)s * C_DIM + c0);
    uint4 pv = *(const uint4*)(Pn   + (size_t)d * C_DIM + c0);
    const __half2* xh = (const __half2*)&xv;
    const __half2* ph = (const __half2*)&pv;
    float r[8];
#pragma unroll
    for (int i = 0; i < 4; i++) {
        float2 xf = __half22float2(xh[i]);
        float2 pf = __half22float2(ph[i]);
        r[i * 2]     = xf.x - pf.x;
        r[i * 2 + 1] = xf.y - pf.y;
    }
    float s1 = 0.f;
#pragma unroll
    for (int i = 0; i < 8; i++) s1 += r[i];
    float mean = warp_sum(s1) * (1.f / 256.f);
    float s2 = 0.f;
#pragma unroll
    for (int i = 0; i < 8; i++) { float t = r[i] - mean; s2 += t * t; }
    float inv = rsqrtf(warp_sum(s2) * (1.f / 256.f) + EPS_LN);
    float4 g0 = *(const float4*)(gg + c0), g1 = *(const float4*)(gg + c0 + 4);
    float4 e0 = *(const float4*)(bb + c0), e1 = *(const float4*)(bb + c0 + 4);
    float m0v = (r[0] - mean) * inv * g0.x + e0.x;
    float m1v = (r[1] - mean) * inv * g0.y + e0.y;
    float m2v = (r[2] - mean) * inv * g0.z + e0.z;
    float m3v = (r[3] - mean) * inv * g0.w + e0.w;
    float m4v = (r[4] - mean) * inv * g1.x + e1.x;
    float m5v = (r[5] - mean) * inv * g1.y + e1.y;
    float m6v = (r[6] - mean) * inv * g1.z + e1.z;
    float m7v = (r[7] - mean) * inv * g1.w + e1.w;
    float* dstp = agg + (size_t)d * C_DIM + c0;
    asm volatile("red.global.add.v4.f32 [%0], {%1,%2,%3,%4};"
                 :: "l"(dstp), "f"(m0v), "f"(m1v), "f"(m2v), "f"(m3v) : "memory");
    asm volatile("red.global.add.v4.f32 [%0], {%1,%2,%3,%4};"
                 :: "l"(dstp + 4), "f"(m4v), "f"(m5v), "f"(m6v), "f"(m7v) : "memory");
}

// agg/max(cnt,1) -> fp16; re-zeros agg in place (keeps it clean for next conv / replay)
__global__ void norm_agg_f16_kernel(float* __restrict__ agg,
                                    const float* __restrict__ cnt,
                                    f16* __restrict__ out, int n)
{
    int idx = blockIdx.x * blockDim.x + threadIdx.x;
    if (idx >= n * 64) return;
    int row = idx >> 6;
    float inv = 1.f / fmaxf(__ldg(cnt + row), 1.f);
    float4* ap = ((float4*)agg) + idx;
    float4 v = *ap;
    *ap = make_float4(0.f, 0.f, 0.f, 0.f);
    *(uint2*)(out + (size_t)idx * 4) =
        make_uint2(pack_h2(v.x * inv, v.y * inv), pack_h2(v.z * inv, v.w * inv));
}

// out = relu(LN(X)*g+b); fp32 out (nullable), fp16 out (nullable)
__global__ void node_ln_relu_kernel(const float* __restrict__ X,
                                    const float* __restrict__ gg, const float* __restrict__ bb,
                                    float* __restrict__ out, f16* __restrict__ outh, int M)
{
    int w = (blockIdx.x * blockDim.x + threadIdx.x) >> 5;
    int lane = threadIdx.x & 31;
    if (w >= M) return;
    int c0 = lane << 3;
    const float4* xp = (const float4*)(X + (size_t)w * C_DIM + c0);
    float4 a0 = xp[0], a1 = xp[1];
    float r[8] = {a0.x, a0.y, a0.z, a0.w, a1.x, a1.y, a1.z, a1.w};
    float s1 = 0.f;
#pragma unroll
    for (int i = 0; i < 8; i++) s1 += r[i];
    float mean = warp_sum(s1) * (1.f / 256.f);
    float s2 = 0.f;
#pragma unroll
    for (int i = 0; i < 8; i++) { float t = r[i] - mean; s2 += t * t; }
    float inv = rsqrtf(warp_sum(s2) * (1.f / 256.f) + EPS_LN);
    float4 g0 = *(const float4*)(gg + c0), g1 = *(const float4*)(gg + c0 + 4);
    float4 e0 = *(const float4*)(bb + c0), e1 = *(const float4*)(bb + c0 + 4);
    float o[8];
    o[0] = fmaxf((r[0] - mean) * inv * g0.x + e0.x, 0.f);
    o[1] = fmaxf((r[1] - mean) * inv * g0.y + e0.y, 0.f);
    o[2] = fmaxf((r[2] - mean) * inv * g0.z + e0.z, 0.f);
    o[3] = fmaxf((r[3] - mean) * inv * g0.w + e0.w, 0.f);
    o[4] = fmaxf((r[4] - mean) * inv * g1.x + e1.x, 0.f);
    o[5] = fmaxf((r[5] - mean) * inv * g1.y + e1.y, 0.f);
    o[6] = fmaxf((r[6] - mean) * inv * g1.z + e1.z, 0.f);
    o[7] = fmaxf((r[7] - mean) * inv * g1.w + e1.w, 0.f);
    if (out) {
        float4* op = (float4*)(out + (size_t)w * C_DIM + c0);
        op[0] = make_float4(o[0], o[1], o[2], o[3]);
        op[1] = make_float4(o[4], o[5], o[6], o[7]);
    }
    if (outh) {
        *(uint4*)(outh + (size_t)w * C_DIM + c0) =
            make_uint4(pack_h2(o[0], o[1]), pack_h2(o[2], o[3]),
                       pack_h2(o[4], o[5]), pack_h2(o[6], o[7]));
    }
}

// ---------------- host ----------------
extern "C" void kernel_launch(void* const* d_in, const int* in_sizes, int n_in,
                              void* d_out, int out_size)
{
    const float* x_user = (const float*)d_in[0];
    const float* x_item = (const float*)d_in[1];
    const float* pw1    = (const float*)d_in[2];
    const float* pb1    = (const float*)d_in[3];
    const float* pw2    = (const float*)d_in[4];
    const float* pb2    = (const float*)d_in[5];
    const float* msg_g  = (const float*)d_in[6];
    const float* msg_b  = (const float*)d_in[7];
    const float* lin_w  = (const float*)d_in[8];
    const float* lin_b  = (const float*)d_in[9];
    const float* node_g = (const float*)d_in[10];
    const float* node_b = (const float*)d_in[11];
    const int*   ei_ui  = (const int*)d_in[12];
    const int*   ei_iu  = (const int*)d_in[13];

    const int NUn = in_sizes[0] / C_DIM;
    const int NIn = in_sizes[1] / C_DIM;
    const int nE0 = in_sizes[12] / 2;
    const int nE1 = in_sizes[13] / 2;
    const int Lm = 2;

    float *aggb, *new_u, *new_i, *cnt_i, *cnt_u;
    f16 *xu_f, *xi_f, *h_f, *a_f, *p_f, *w_f;
    cudaGetSymbolAddress((void**)&aggb, g_agg);
    cudaGetSymbolAddress((void**)&new_u, g_new_u);
    cudaGetSymbolAddress((void**)&new_i, g_new_i);
    cudaGetSymbolAddress((void**)&cnt_i, g_cnt_i);
    cudaGetSymbolAddress((void**)&cnt_u, g_cnt_u);
    cudaGetSymbolAddress((void**)&xu_f, g_xu_f);
    cudaGetSymbolAddress((void**)&xi_f, g_xi_f);
    cudaGetSymbolAddress((void**)&h_f, g_h_f);
    cudaGetSymbolAddress((void**)&a_f, g_a_f);
    cudaGetSymbolAddress((void**)&p_f, g_p_f);
    cudaGetSymbolAddress((void**)&w_f, g_w);

    cudaFuncSetAttribute(gemm_mma<0>, cudaFuncAttributeMaxDynamicSharedMemorySize, GEMM_SMEM);
    cudaFuncSetAttribute(gemm_mma<1>, cudaFuncAttributeMaxDynamicSharedMemorySize, GEMM_SMEM);
    cudaFuncSetAttribute(gemm_mma<3>, cudaFuncAttributeMaxDynamicSharedMemorySize, GEMM_SMEM);

    // all weights in ONE launch
    convert_all_w_kernel<<<(4 * WSTRIDE + 255) / 256, 256>>>(pw1, pw2, lin_w, w_f);
    f32_to_f16_kernel<<<(NUn * 64 + 255) / 256, 256>>>(x_user, xu_f, NUn * 64);
    f32_to_f16_kernel<<<(NIn * 64 + 255) / 256, 256>>>(x_item, xi_f, NIn * 64);

    // degree counts (edge arrays shared across layers)
    cudaMemsetAsync(cnt_i, 0, (size_t)NIn * sizeof(float));
    cudaMemsetAsync(cnt_u, 0, (size_t)NUn * sizeof(float));
    count_kernel<<<(nE0 + 255) / 256, 256>>>(ei_ui + nE0, cnt_i, nE0);
    count_kernel<<<(nE1 + 255) / 256, 256>>>(ei_iu + nE1, cnt_u, nE1);

    // agg is zero-initialized at load and re-zeroed by norm_agg each use.

    float* out_f = (float*)d_out;

    for (int l = 0; l < Lm; l++) {
        bool last = (l == Lm - 1);
        // ---- conv: dst = item, src = user (params [l,0]) ----
        {
            int t = l * 2 + 0;
            size_t wo = (size_t)t * WSTRIDE;
            dim3 g4((NIn + 127) / 128, 4), g2((NIn + 127) / 128, 2);
            gemm_mma<3><<<g4, 256, GEMM_SMEM>>>(xi_f, w_f + wo,
                pb1 + (size_t)t * C_DIM, lin_b + (size_t)t * C_DIM, new_i, h_f, NIn);
            gemm_mma<0><<<g2, 256, GEMM_SMEM>>>(h_f, w_f + wo + 131072,
                pb2 + (size_t)t * C_DIM, (float*)0, (float*)0, p_f, NIn);
            edge_msg_kernel<<<(nE0 * 32 + 255) / 256, 256>>>(xu_f, p_f, ei_ui,
                msg_g + (size_t)t * C_DIM, msg_b + (size_t)t * C_DIM, aggb, nE0);
            norm_agg_f16_kernel<<<(NIn * 64 + 255) / 256, 256>>>(aggb, cnt_i, a_f, NIn);
            gemm_mma<1><<<g2, 256, GEMM_SMEM>>>(a_f, w_f + wo + 196608,
                (float*)0, (float*)0, new_i, (f16*)0, NIn);
        }
        // ---- conv: dst = user, src = item (params [l,1]) ----
        {
            int t = l * 2 + 1;
            size_t wo = (size_t)t * WSTRIDE;
            dim3 g4((NUn + 127) / 128, 4), g2((NUn + 127) / 128, 2);
            gemm_mma<3><<<g4, 256, GEMM_SMEM>>>(xu_f, w_f + wo,
                pb1 + (size_t)t * C_DIM, lin_b + (size_t)t * C_DIM, new_u, h_f, NUn);
            gemm_mma<0><<<g2, 256, GEMM_SMEM>>>(h_f, w_f + wo + 131072,
                pb2 + (size_t)t * C_DIM, (float*)0, (float*)0, p_f, NUn);
            edge_msg_kernel<<<(nE1 * 32 + 255) / 256, 256>>>(xi_f, p_f, ei_iu,
                msg_g + (size_t)t * C_DIM, msg_b + (size_t)t * C_DIM, aggb, nE1);
            norm_agg_f16_kernel<<<(NUn * 64 + 255) / 256, 256>>>(aggb, cnt_u, a_f, NUn);
            gemm_mma<1><<<g2, 256, GEMM_SMEM>>>(a_f, w_f + wo + 196608,
                (float*)0, (float*)0, new_u, (f16*)0, NUn);
        }
        // ---- node LN + relu ----
        node_ln_relu_kernel<<<(NUn * 32 + 255) / 256, 256>>>(new_u,
            node_g + (size_t)(l * 2 + 0) * C_DIM, node_b + (size_t)(l * 2 + 0) * C_DIM,
            last ? out_f : (float*)0, last ? (f16*)0 : xu_f, NUn);
        node_ln_relu_kernel<<<(NIn * 32 + 255) / 256, 256>>>(new_i,
            node_g + (size_t)(l * 2 + 1) * C_DIM, node_b + (size_t)(l * 2 + 1) * C_DIM,
            last ? (out_f + (size_t)NUn * C_DIM) : (float*)0, last ? (f16*)0 : xi_f, NIn);
    }
    (void)n_in; (void)out_size;
}

// round 15
// speedup vs baseline: 1.5172x; 1.5172x over previous
#include <cuda_runtime.h>
#include <cuda_fp16.h>
#include <cstdint>

#define C_DIM   256
#define MAXN    100000
#define EPS_LN  1e-5f

typedef __half f16;

// ---------------- device scratch ----------------
__device__ float g_agg  [MAXN * C_DIM];
__device__ float g_new_u[MAXN * C_DIM];
__device__ float g_new_i[MAXN * C_DIM];
__device__ float g_cnt_i[MAXN];
__device__ float g_cnt_u[MAXN];

__device__ __align__(16) f16 g_xu_f[MAXN * C_DIM];
__device__ __align__(16) f16 g_xi_f[MAXN * C_DIM];
__device__ __align__(16) f16 g_h_f [MAXN * C_DIM];
__device__ __align__(16) f16 g_a_f [MAXN * C_DIM];
__device__ __align__(16) f16 g_p_f [MAXN * C_DIM];

// per conv: W1T | WxT | W2T | WaT, each [256,256] K-major [n,k]
#define WSTRIDE (262144)
__device__ __align__(16) f16 g_w[4 * WSTRIDE];

// ---------------- helpers ----------------
__device__ __forceinline__ uint32_t smem_u32(const void* p) {
    uint32_t a;
    asm("{ .reg .u64 t; cvta.to.shared.u64 t, %1; cvt.u32.u64 %0, t; }" : "=r"(a) : "l"(p));
    return a;
}
__device__ __forceinline__ void cp16(uint32_t s, const void* g) {
    asm volatile("cp.async.cg.shared.global [%0], [%1], 16;" :: "r"(s), "l"(g));
}
__device__ __forceinline__ void cp_commit() { asm volatile("cp.async.commit_group;" ::: "memory"); }
template<int N> __device__ __forceinline__ void cp_wait() {
    asm volatile("cp.async.wait_group %0;" :: "n"(N) : "memory");
}
#define SW128(o) ((o) ^ (((o) >> 3) & 0x70))

__device__ __forceinline__ uint32_t pack_h2(float a, float b) {
    __half2 t = __halves2half2(__float2half_rn(a), __float2half_rn(b));
    return *reinterpret_cast<uint32_t*>(&t);
}

#define LDSM4(r0, r1, r2, r3, addr) \
    asm volatile("ldmatrix.sync.aligned.m8n8.x4.shared.b16 {%0,%1,%2,%3}, [%4];" \
                 : "=r"(r0), "=r"(r1), "=r"(r2), "=r"(r3) : "r"(addr))

#define MMA16816F(d, a, b0, b1) \
    asm volatile("mma.sync.aligned.m16n8k16.row.col.f32.f16.f16.f32 " \
                 "{%0,%1,%2,%3}, {%4,%5,%6,%7}, {%8,%9}, {%0,%1,%2,%3};" \
                 : "+f"((d)[0]), "+f"((d)[1]), "+f"((d)[2]), "+f"((d)[3]) \
                 : "r"((a)[0]), "r"((a)[1]), "r"((a)[2]), "r"((a)[3]), \
                   "r"(b0), "r"(b1))

__device__ __forceinline__ float warp_sum(float v) {
#pragma unroll
    for (int o = 16; o > 0; o >>= 1) v += __shfl_xor_sync(0xffffffffu, v, o);
    return v;
}

// ---------------- warp-MMA GEMM (single-term fp16) ----------------
// out[M, *] = A[M,256] @ B^T; A,B fp16 (B K-major [n,256]).
// Block tile 128(M) x 128(N), 256 threads, 8 warps (2m x 4n), warp tile 64x32.
// EPI 0: outH = f16(D + bias1)                            (P)
// EPI 1: outF += D                                        (new += agg@Wa)
// EPI 3: cols<256 -> outH = f16(relu(D+bias1)); cols>=256 -> outF = D + bias2
#define CHUNK_BYTES 32768
#define GEMM_SMEM   (2 * CHUNK_BYTES)

__device__ __forceinline__ void gemm_load_chunk(
    uint32_t sbuf, int tid, int m0, int n0, int M, int c,
    const f16* Af, const f16* Bf)
{
    const int k0 = c * 64;
#pragma unroll
    for (int i = 0; i < 4; i++) {              // A: 128 rows x 128B
        int idx = tid + i * 256;
        int r = idx >> 3, u = idx & 7;
        int rg = min(m0 + r, M - 1);
        uint32_t so = SW128((uint32_t)(r * 128 + u * 16));
        cp16(sbuf + so, (const char*)(Af + (size_t)rg * C_DIM + k0) + u * 16);
    }
#pragma unroll
    for (int i = 0; i < 4; i++) {              // B: 128 n-rows x 128B
        int idx = tid + i * 256;
        int r = idx >> 3, u = idx & 7;
        uint32_t so = SW128((uint32_t)(r * 128 + u * 16));
        cp16(sbuf + 16384 + so, (const char*)(Bf + (size_t)(n0 + r) * C_DIM + k0) + u * 16);
    }
}

template<int EPI>
__global__ __launch_bounds__(256, 2)
void gemm_mma(const f16* __restrict__ Af, const f16* __restrict__ Bf,
              const float* __restrict__ bias1, const float* __restrict__ bias2,
              float* __restrict__ outF, f16* __restrict__ outH, int M)
{
    extern __shared__ char smem[];
    const uint32_t sb = smem_u32(smem);
    const int tid  = threadIdx.x;
    const int lane = tid & 31;
    const int wid  = tid >> 5;
    const int wm   = wid >> 2;
    const int wn   = wid & 3;
    const int m0   = blockIdx.x * 128;
    const int n0   = blockIdx.y * 128;

    const uint32_t aOff = (uint32_t)((wm * 64 + (lane & 15)) * 128 + ((lane >> 4) << 4));
    const uint32_t bOff = (uint32_t)((wn * 32 + (lane & 7) + ((lane >> 4) << 3)) * 128
                                     + (((lane >> 3) & 1) << 4));

    float D[4][4][4];
#pragma unroll
    for (int g = 0; g < 4; g++)
#pragma unroll
        for (int n = 0; n < 4; n++)
#pragma unroll
            for (int q = 0; q < 4; q++) D[g][n][q] = 0.f;

    gemm_load_chunk(sb, tid, m0, n0, M, 0, Af, Bf);
    cp_commit();

#pragma unroll
    for (int c = 0; c < 4; c++) {
        if (c + 1 < 4) {
            gemm_load_chunk(sb + (uint32_t)((c + 1) & 1) * CHUNK_BYTES,
                            tid, m0, n0, M, c + 1, Af, Bf);
            cp_commit();
            cp_wait<1>();
        } else {
            cp_wait<0>();
        }
        __syncthreads();

        const uint32_t base = sb + (uint32_t)(c & 1) * CHUNK_BYTES;
#pragma unroll
        for (int ks = 0; ks < 4; ks++) {
            const uint32_t kb = (uint32_t)(ks * 32);
            uint32_t af[4][4];
#pragma unroll
            for (int g = 0; g < 4; g++) {
                uint32_t sw = SW128(aOff + (uint32_t)(g * 2048) + kb);
                LDSM4(af[g][0], af[g][1], af[g][2], af[g][3], base + sw);
            }
            uint32_t bh[2][4];
#pragma unroll
            for (int p = 0; p < 2; p++) {
                uint32_t sw = SW128(bOff + (uint32_t)(p * 2048) + kb);
                LDSM4(bh[p][0], bh[p][1], bh[p][2], bh[p][3], base + 16384 + sw);
            }
#pragma unroll
            for (int g = 0; g < 4; g++) {
#pragma unroll
                for (int n = 0; n < 4; n++) {
                    const int p = n >> 1, rb = (n & 1) * 2;
                    MMA16816F(D[g][n], af[g], bh[p][rb], bh[p][rb + 1]);
                }
            }
        }
        __syncthreads();
    }

    // ---- epilogue ----
#pragma unroll
    for (int g = 0; g < 4; g++) {
#pragma unroll
        for (int n = 0; n < 4; n++) {
            int r0  = m0 + wm * 64 + g * 16 + (lane >> 2);
            int col = n0 + wn * 32 + n * 8 + (lane & 3) * 2;
            if (EPI == 0) {
                float2 bv = *(const float2*)(bias1 + col);
                if (r0 < M)
                    *(uint32_t*)(outH + (size_t)r0 * C_DIM + col) =
                        pack_h2(D[g][n][0] + bv.x, D[g][n][1] + bv.y);
                if (r0 + 8 < M)
                    *(uint32_t*)(outH + (size_t)(r0 + 8) * C_DIM + col) =
                        pack_h2(D[g][n][2] + bv.x, D[g][n][3] + bv.y);
            } else if (EPI == 1) {
                if (r0 < M) {
                    float2* p = (float2*)(outF + (size_t)r0 * C_DIM + col);
                    float2 o = *p;
                    *p = make_float2(o.x + D[g][n][0], o.y + D[g][n][1]);
                }
                if (r0 + 8 < M) {
                    float2* p = (float2*)(outF + (size_t)(r0 + 8) * C_DIM + col);
                    float2 o = *p;
                    *p = make_float2(o.x + D[g][n][2], o.y + D[g][n][3]);
                }
            } else {  // EPI 3
                if (col < 256) {
                    float2 bv = *(const float2*)(bias1 + col);
                    if (r0 < M)
                        *(uint32_t*)(outH + (size_t)r0 * C_DIM + col) =
                            pack_h2(fmaxf(D[g][n][0] + bv.x, 0.f),
                                    fmaxf(D[g][n][1] + bv.y, 0.f));
                    if (r0 + 8 < M)
                        *(uint32_t*)(outH + (size_t)(r0 + 8) * C_DIM + col) =
                            pack_h2(fmaxf(D[g][n][2] + bv.x, 0.f),
                                    fmaxf(D[g][n][3] + bv.y, 0.f));
                } else {
                    int cf = col - 256;
                    float2 bv = *(const float2*)(bias2 + cf);
                    if (r0 < M)
                        *(float2*)(outF + (size_t)r0 * C_DIM + cf) =
                            make_float2(D[g][n][0] + bv.x, D[g][n][1] + bv.y);
                    if (r0 + 8 < M)
                        *(float2*)(outF + (size_t)(r0 + 8) * C_DIM + cf) =
                            make_float2(D[g][n][2] + bv.x, D[g][n][3] + bv.y);
                }
            }
        }
    }
}

// ---------------- aux kernels ----------------
__global__ void f32_to_f16_kernel(const float* __restrict__ x,
                                  f16* __restrict__ out, int n4)
{
    int idx = blockIdx.x * blockDim.x + threadIdx.x;
    if (idx >= n4) return;
    float4 v = ((const float4*)x)[idx];
    *(uint2*)(out + (size_t)idx * 4) = make_uint2(pack_h2(v.x, v.y), pack_h2(v.z, v.w));
}

// One launch converts ALL weights for all 4 convs into g_w (transposed fp16).
// Layout per conv t: W1T | WxT | W2T | WaT (each 65536 elems).
__global__ void convert_all_w_kernel(const float* __restrict__ pw1,
                                     const float* __restrict__ pw2,
                                     const float* __restrict__ lin_w,
                                     f16* __restrict__ out)
{
    int idx = blockIdx.x * blockDim.x + threadIdx.x;
    if (idx >= 4 * WSTRIDE) return;
    int t   = idx >> 18;
    int rem = idx & (WSTRIDE - 1);
    int m   = rem >> 16;
    int e   = rem & 65535;
    int n   = e >> 8, k = e & 255;
    float v;
    if (m == 0)      v = pw1[(size_t)t * 65536 + k * 256 + n];
    else if (m == 1) v = lin_w[(size_t)t * 131072 + k * 256 + n];
    else if (m == 2) v = pw2[(size_t)t * 65536 + k * 256 + n];
    else             v = lin_w[(size_t)t * 131072 + 65536 + k * 256 + n];
    out[idx] = __float2half_rn(v);
}

__global__ void count_kernel(const int* __restrict__ dst, float* __restrict__ cnt, int nE)
{
    int i = blockIdx.x * blockDim.x + threadIdx.x;
    if (i < nE) atomicAdd(cnt + __ldg(dst + i), 1.0f);
}

// fp16 edge stage: msg = LN(x_src[s] - P[d]) * g + b, red into fp32 agg
__global__ void edge_msg_kernel(const f16* __restrict__ xsrc,
                                const f16* __restrict__ Pn,
                                const int* __restrict__ ei,
                                const float* __restrict__ gg,
                                const float* __restrict__ bb,
                                float* __restrict__ agg, int nE)
{
    int w = (blockIdx.x * blockDim.x + threadIdx.x) >> 5;
    int lane = threadIdx.x & 31;
    if (w >= nE) return;
    int s = __ldg(ei + w);
    int d = __ldg(ei + nE + w);
    int c0 = lane << 3;

    uint4 xv = *(const uint4*)(xsrc + (size_t)s * C_DIM + c0);
    uint4 pv = *(const uint4*)(Pn   + (size_t)d * C_DIM + c0);
    const __half2* xh = (const __half2*)&xv;
    const __half2* ph = (const __half2*)&pv;
    float r[8];
#pragma unroll
    for (int i = 0; i < 4; i++) {
        float2 xf = __half22float2(xh[i]);
        float2 pf = __half22float2(ph[i]);
        r[i * 2]     = xf.x - pf.x;
        r[i * 2 + 1] = xf.y - pf.y;
    }
    float s1 = 0.f;
#pragma unroll
    for (int i = 0; i < 8; i++) s1 += r[i];
    float mean = warp_sum(s1) * (1.f / 256.f);
    float s2 = 0.f;
#pragma unroll
    for (int i = 0; i < 8; i++) { float t = r[i] - mean; s2 += t * t; }
    float inv = rsqrtf(warp_sum(s2) * (1.f / 256.f) + EPS_LN);
    float4 g0 = *(const float4*)(gg + c0), g1 = *(const float4*)(gg + c0 + 4);
    float4 e0 = *(const float4*)(bb + c0), e1 = *(const float4*)(bb + c0 + 4);
    float m0v = (r[0] - mean) * inv * g0.x + e0.x;
    float m1v = (r[1] - mean) * inv * g0.y + e0.y;
    float m2v = (r[2] - mean) * inv * g0.z + e0.z;
    float m3v = (r[3] - mean) * inv * g0.w + e0.w;
    float m4v = (r[4] - mean) * inv * g1.x + e1.x;
    float m5v = (r[5] - mean) * inv * g1.y + e1.y;
    float m6v = (r[6] - mean) * inv * g1.z + e1.z;
    float m7v = (r[7] - mean) * inv * g1.w + e1.w;
    float* dstp = agg + (size_t)d * C_DIM + c0;
    asm volatile("red.global.add.v4.f32 [%0], {%1,%2,%3,%4};"
                 :: "l"(dstp), "f"(m0v), "f"(m1v), "f"(m2v), "f"(m3v) : "memory");
    asm volatile("red.global.add.v4.f32 [%0], {%1,%2,%3,%4};"
                 :: "l"(dstp + 4), "f"(m4v), "f"(m5v), "f"(m6v), "f"(m7v) : "memory");
}

// agg/max(cnt,1) -> fp16 (read-only on agg; memset handles zeroing)
__global__ void norm_agg_f16_kernel(const float* __restrict__ agg,
                                    const float* __restrict__ cnt,
                                    f16* __restrict__ out, int n)
{
    int idx = blockIdx.x * blockDim.x + threadIdx.x;
    if (idx >= n * 64) return;
    int row = idx >> 6;
    float inv = 1.f / fmaxf(__ldg(cnt + row), 1.f);
    float4 v = ((const float4*)agg)[idx];
    *(uint2*)(out + (size_t)idx * 4) =
        make_uint2(pack_h2(v.x * inv, v.y * inv), pack_h2(v.z * inv, v.w * inv));
}

// out = relu(LN(X)*g+b); fp32 out (nullable), fp16 out (nullable)
__global__ void node_ln_relu_kernel(const float* __restrict__ X,
                                    const float* __restrict__ gg, const float* __restrict__ bb,
                                    float* __restrict__ out, f16* __restrict__ outh, int M)
{
    int w = (blockIdx.x * blockDim.x + threadIdx.x) >> 5;
    int lane = threadIdx.x & 31;
    if (w >= M) return;
    int c0 = lane << 3;
    const float4* xp = (const float4*)(X + (size_t)w * C_DIM + c0);
    float4 a0 = xp[0], a1 = xp[1];
    float r[8] = {a0.x, a0.y, a0.z, a0.w, a1.x, a1.y, a1.z, a1.w};
    float s1 = 0.f;
#pragma unroll
    for (int i = 0; i < 8; i++) s1 += r[i];
    float mean = warp_sum(s1) * (1.f / 256.f);
    float s2 = 0.f;
#pragma unroll
    for (int i = 0; i < 8; i++) { float t = r[i] - mean; s2 += t * t; }
    float inv = rsqrtf(warp_sum(s2) * (1.f / 256.f) + EPS_LN);
    float4 g0 = *(const float4*)(gg + c0), g1 = *(const float4*)(gg + c0 + 4);
    float4 e0 = *(const float4*)(bb + c0), e1 = *(const float4*)(bb + c0 + 4);
    float o[8];
    o[0] = fmaxf((r[0] - mean) * inv * g0.x + e0.x, 0.f);
    o[1] = fmaxf((r[1] - mean) * inv * g0.y + e0.y, 0.f);
    o[2] = fmaxf((r[2] - mean) * inv * g0.z + e0.z, 0.f);
    o[3] = fmaxf((r[3] - mean) * inv * g0.w + e0.w, 0.f);
    o[4] = fmaxf((r[4] - mean) * inv * g1.x + e1.x, 0.f);
    o[5] = fmaxf((r[5] - mean) * inv * g1.y + e1.y, 0.f);
    o[6] = fmaxf((r[6] - mean) * inv * g1.z + e1.z, 0.f);
    o[7] = fmaxf((r[7] - mean) * inv * g1.w + e1.w, 0.f);
    if (out) {
        float4* op = (float4*)(out + (size_t)w * C_DIM + c0);
        op[0] = make_float4(o[0], o[1], o[2], o[3]);
        op[1] = make_float4(o[4], o[5], o[6], o[7]);
    }
    if (outh) {
        *(uint4*)(outh + (size_t)w * C_DIM + c0) =
            make_uint4(pack_h2(o[0], o[1]), pack_h2(o[2], o[3]),
                       pack_h2(o[4], o[5]), pack_h2(o[6], o[7]));
    }
}

// ---------------- host ----------------
extern "C" void kernel_launch(void* const* d_in, const int* in_sizes, int n_in,
                              void* d_out, int out_size)
{
    const float* x_user = (const float*)d_in[0];
    const float* x_item = (const float*)d_in[1];
    const float* pw1    = (const float*)d_in[2];
    const float* pb1    = (const float*)d_in[3];
    const float* pw2    = (const float*)d_in[4];
    const float* pb2    = (const float*)d_in[5];
    const float* msg_g  = (const float*)d_in[6];
    const float* msg_b  = (const float*)d_in[7];
    const float* lin_w  = (const float*)d_in[8];
    const float* lin_b  = (const float*)d_in[9];
    const float* node_g = (const float*)d_in[10];
    const float* node_b = (const float*)d_in[11];
    const int*   ei_ui  = (const int*)d_in[12];
    const int*   ei_iu  = (const int*)d_in[13];

    const int NUn = in_sizes[0] / C_DIM;
    const int NIn = in_sizes[1] / C_DIM;
    const int nE0 = in_sizes[12] / 2;
    const int nE1 = in_sizes[13] / 2;
    const int Lm = 2;

    float *aggb, *new_u, *new_i, *cnt_i, *cnt_u;
    f16 *xu_f, *xi_f, *h_f, *a_f, *p_f, *w_f;
    cudaGetSymbolAddress((void**)&aggb, g_agg);
    cudaGetSymbolAddress((void**)&new_u, g_new_u);
    cudaGetSymbolAddress((void**)&new_i, g_new_i);
    cudaGetSymbolAddress((void**)&cnt_i, g_cnt_i);
    cudaGetSymbolAddress((void**)&cnt_u, g_cnt_u);
    cudaGetSymbolAddress((void**)&xu_f, g_xu_f);
    cudaGetSymbolAddress((void**)&xi_f, g_xi_f);
    cudaGetSymbolAddress((void**)&h_f, g_h_f);
    cudaGetSymbolAddress((void**)&a_f, g_a_f);
    cudaGetSymbolAddress((void**)&p_f, g_p_f);
    cudaGetSymbolAddress((void**)&w_f, g_w);

    cudaFuncSetAttribute(gemm_mma<0>, cudaFuncAttributeMaxDynamicSharedMemorySize, GEMM_SMEM);
    cudaFuncSetAttribute(gemm_mma<1>, cudaFuncAttributeMaxDynamicSharedMemorySize, GEMM_SMEM);
    cudaFuncSetAttribute(gemm_mma<3>, cudaFuncAttributeMaxDynamicSharedMemorySize, GEMM_SMEM);

    // all weights in ONE launch
    convert_all_w_kernel<<<(4 * WSTRIDE + 255) / 256, 256>>>(pw1, pw2, lin_w, w_f);
    f32_to_f16_kernel<<<(NUn * 64 + 255) / 256, 256>>>(x_user, xu_f, NUn * 64);
    f32_to_f16_kernel<<<(NIn * 64 + 255) / 256, 256>>>(x_item, xi_f, NIn * 64);

    // degree counts (edge arrays shared across layers)
    cudaMemsetAsync(cnt_i, 0, (size_t)NIn * sizeof(float));
    cudaMemsetAsync(cnt_u, 0, (size_t)NUn * sizeof(float));
    count_kernel<<<(nE0 + 255) / 256, 256>>>(ei_ui + nE0, cnt_i, nE0);
    count_kernel<<<(nE1 + 255) / 256, 256>>>(ei_iu + nE1, cnt_u, nE1);

    float* out_f = (float*)d_out;

    for (int l = 0; l < Lm; l++) {
        bool last = (l == Lm - 1);
        // ---- conv: dst = item, src = user (params [l,0]) ----
        {
            int t = l * 2 + 0;
            size_t wo = (size_t)t * WSTRIDE;
            dim3 g4((NIn + 127) / 128, 4), g2((NIn + 127) / 128, 2);
            gemm_mma<3><<<g4, 256, GEMM_SMEM>>>(xi_f, w_f + wo,
                pb1 + (size_t)t * C_DIM, lin_b + (size_t)t * C_DIM, new_i, h_f, NIn);
            gemm_mma<0><<<g2, 256, GEMM_SMEM>>>(h_f, w_f + wo + 131072,
                pb2 + (size_t)t * C_DIM, (float*)0, (float*)0, p_f, NIn);
            // memset directly before edge kernel keeps agg resident in L2 for the atomics
            cudaMemsetAsync(aggb, 0, (size_t)NIn * C_DIM * sizeof(float));
            edge_msg_kernel<<<(nE0 * 32 + 255) / 256, 256>>>(xu_f, p_f, ei_ui,
                msg_g + (size_t)t * C_DIM, msg_b + (size_t)t * C_DIM, aggb, nE0);
            norm_agg_f16_kernel<<<(NIn * 64 + 255) / 256, 256>>>(aggb, cnt_i, a_f, NIn);
            gemm_mma<1><<<g2, 256, GEMM_SMEM>>>(a_f, w_f + wo + 196608,
                (float*)0, (float*)0, new_i, (f16*)0, NIn);
        }
        // ---- conv: dst = user, src = item (params [l,1]) ----
        {
            int t = l * 2 + 1;
            size_t wo = (size_t)t * WSTRIDE;
            dim3 g4((NUn + 127) / 128, 4), g2((NUn + 127) / 128, 2);
            gemm_mma<3><<<g4, 256, GEMM_SMEM>>>(xu_f, w_f + wo,
                pb1 + (size_t)t * C_DIM, lin_b + (size_t)t * C_DIM, new_u, h_f, NUn);
            gemm_mma<0><<<g2, 256, GEMM_SMEM>>>(h_f, w_f + wo + 131072,
                pb2 + (size_t)t * C_DIM, (float*)0, (float*)0, p_f, NUn);
            cudaMemsetAsync(aggb, 0, (size_t)NUn * C_DIM * sizeof(float));
            edge_msg_kernel<<<(nE1 * 32 + 255) / 256, 256>>>(xi_f, p_f, ei_iu,
                msg_g + (size_t)t * C_DIM, msg_b + (size_t)t * C_DIM, aggb, nE1);
            norm_agg_f16_kernel<<<(NUn * 64 + 255) / 256, 256>>>(aggb, cnt_u, a_f, NUn);
            gemm_mma<1><<<g2, 256, GEMM_SMEM>>>(a_f, w_f + wo + 196608,
                (float*)0, (float*)0, new_u, (f16*)0, NUn);
        }
        // ---- node LN + relu ----
        node_ln_relu_kernel<<<(NUn * 32 + 255) / 256, 256>>>(new_u,
            node_g + (size_t)(l * 2 + 0) * C_DIM, node_b + (size_t)(l * 2 + 0) * C_DIM,
            last ? out_f : (float*)0, last ? (f16*)0 : xu_f, NUn);
        node_ln_relu_kernel<<<(NIn * 32 + 255) / 256, 256>>>(new_i,
            node_g + (size_t)(l * 2 + 1) * C_DIM, node_b + (size_t)(l * 2 + 1) * C_DIM,
            last ? (out_f + (size_t)NUn * C_DIM) : (float*)0, last ? (f16*)0 : xi_f, NIn);
    }
    (void)n_in; (void)out_size;
}

// round 16
// speedup vs baseline: 1.7774x; 1.1715x over previous
#include <cuda_runtime.h>
#include <cuda_fp16.h>
#include <cstdint>

#define C_DIM   256
#define MAXN    100000
#define EPS_LN  1e-5f

typedef __half f16;

// ---------------- device scratch ----------------
__device__ float g_agg  [MAXN * C_DIM];
__device__ float g_new_u[MAXN * C_DIM];
__device__ float g_new_i[MAXN * C_DIM];
__device__ float g_cnt_i[MAXN];
__device__ float g_cnt_u[MAXN];

__device__ __align__(16) f16 g_xu_f[MAXN * C_DIM];
__device__ __align__(16) f16 g_xi_f[MAXN * C_DIM];
__device__ __align__(16) f16 g_h_f [MAXN * C_DIM];
__device__ __align__(16) f16 g_a_f [MAXN * C_DIM];
__device__ __align__(16) f16 g_p_f [MAXN * C_DIM];

// per conv: W1T[256,256] | W2T[256,256] | WCATT[256,512]
// W1T/W2T: dst[n*256+k]; WCATT: dst[n*512+k] with k<256 = Wx, k>=256 = Wa
#define WSTRIDE (262144)
__device__ __align__(16) f16 g_w[4 * WSTRIDE];

// ---------------- helpers ----------------
__device__ __forceinline__ uint32_t smem_u32(const void* p) {
    uint32_t a;
    asm("{ .reg .u64 t; cvta.to.shared.u64 t, %1; cvt.u32.u64 %0, t; }" : "=r"(a) : "l"(p));
    return a;
}
__device__ __forceinline__ void cp16(uint32_t s, const void* g) {
    asm volatile("cp.async.cg.shared.global [%0], [%1], 16;" :: "r"(s), "l"(g));
}
__device__ __forceinline__ void cp_commit() { asm volatile("cp.async.commit_group;" ::: "memory"); }
template<int N> __device__ __forceinline__ void cp_wait() {
    asm volatile("cp.async.wait_group %0;" :: "n"(N) : "memory");
}
#define SW128(o) ((o) ^ (((o) >> 3) & 0x70))

__device__ __forceinline__ uint32_t pack_h2(float a, float b) {
    __half2 t = __halves2half2(__float2half_rn(a), __float2half_rn(b));
    return *reinterpret_cast<uint32_t*>(&t);
}

#define LDSM4(r0, r1, r2, r3, addr) \
    asm volatile("ldmatrix.sync.aligned.m8n8.x4.shared.b16 {%0,%1,%2,%3}, [%4];" \
                 : "=r"(r0), "=r"(r1), "=r"(r2), "=r"(r3) : "r"(addr))

#define MMA16816F(d, a, b0, b1) \
    asm volatile("mma.sync.aligned.m16n8k16.row.col.f32.f16.f16.f32 " \
                 "{%0,%1,%2,%3}, {%4,%5,%6,%7}, {%8,%9}, {%0,%1,%2,%3};" \
                 : "+f"((d)[0]), "+f"((d)[1]), "+f"((d)[2]), "+f"((d)[3]) \
                 : "r"((a)[0]), "r"((a)[1]), "r"((a)[2]), "r"((a)[3]), \
                   "r"(b0), "r"(b1))

__device__ __forceinline__ float warp_sum(float v) {
#pragma unroll
    for (int o = 16; o > 0; o >>= 1) v += __shfl_xor_sync(0xffffffffu, v, o);
    return v;
}

#define CHUNK_BYTES 32768
#define GEMM_SMEM   (2 * CHUNK_BYTES)

// ---------------- mainloop core (shared by both GEMMs) ----------------
struct TileCtx {
    uint32_t sb, aOff, bOff;
    int tid, lane, wid, wm, wn, m0, n0;
};

__device__ __forceinline__ void tile_init(TileCtx& c) {
    c.tid  = threadIdx.x;
    c.lane = c.tid & 31;
    c.wid  = c.tid >> 5;
    c.wm   = c.wid >> 2;
    c.wn   = c.wid & 3;
    c.m0   = blockIdx.x * 128;
    c.n0   = blockIdx.y * 128;
    c.aOff = (uint32_t)((c.wm * 64 + (c.lane & 15)) * 128 + ((c.lane >> 4) << 4));
    c.bOff = (uint32_t)((c.wn * 32 + (c.lane & 7) + ((c.lane >> 4) << 3)) * 128
                        + (((c.lane >> 3) & 1) << 4));
}

__device__ __forceinline__ void mma_chunk(const TileCtx& c, uint32_t base, float D[4][4][4]) {
#pragma unroll
    for (int ks = 0; ks < 4; ks++) {
        const uint32_t kb = (uint32_t)(ks * 32);
        uint32_t af[4][4];
#pragma unroll
        for (int g = 0; g < 4; g++) {
            uint32_t sw = SW128(c.aOff + (uint32_t)(g * 2048) + kb);
            LDSM4(af[g][0], af[g][1], af[g][2], af[g][3], base + sw);
        }
        uint32_t bh[2][4];
#pragma unroll
        for (int p = 0; p < 2; p++) {
            uint32_t sw = SW128(c.bOff + (uint32_t)(p * 2048) + kb);
            LDSM4(bh[p][0], bh[p][1], bh[p][2], bh[p][3], base + 16384 + sw);
        }
#pragma unroll
        for (int g = 0; g < 4; g++) {
#pragma unroll
            for (int n = 0; n < 4; n++) {
                const int p = n >> 1, rb = (n & 1) * 2;
                MMA16816F(D[g][n], af[g], bh[p][rb], bh[p][rb + 1]);
            }
        }
    }
}

// ---------------- GEMM A: K=256, f16 out (optional relu) ----------------
// EPI 0: outH = f16(D + bias)        (P)
// EPI 2: outH = f16(relu(D + bias))  (H)
__device__ __forceinline__ void load_chunk_k256(
    uint32_t sbuf, int tid, int m0, int n0, int M, int c,
    const f16* Af, const f16* Bf)
{
    const int k0 = c * 64;
#pragma unroll
    for (int i = 0; i < 4; i++) {
        int idx = tid + i * 256;
        int r = idx >> 3, u = idx & 7;
        int rg = min(m0 + r, M - 1);
        uint32_t so = SW128((uint32_t)(r * 128 + u * 16));
        cp16(sbuf + so, (const char*)(Af + (size_t)rg * C_DIM + k0) + u * 16);
    }
#pragma unroll
    for (int i = 0; i < 4; i++) {
        int idx = tid + i * 256;
        int r = idx >> 3, u = idx & 7;
        uint32_t so = SW128((uint32_t)(r * 128 + u * 16));
        cp16(sbuf + 16384 + so, (const char*)(Bf + (size_t)(n0 + r) * C_DIM + k0) + u * 16);
    }
}

template<int EPI>
__global__ __launch_bounds__(256, 2)
void gemm_h(const f16* __restrict__ Af, const f16* __restrict__ Bf,
            const float* __restrict__ bias, f16* __restrict__ outH, int M)
{
    extern __shared__ char smem[];
    TileCtx c; tile_init(c);
    c.sb = smem_u32(smem);

    float D[4][4][4];
#pragma unroll
    for (int g = 0; g < 4; g++)
#pragma unroll
        for (int n = 0; n < 4; n++)
#pragma unroll
            for (int q = 0; q < 4; q++) D[g][n][q] = 0.f;

    load_chunk_k256(c.sb, c.tid, c.m0, c.n0, M, 0, Af, Bf);
    cp_commit();

#pragma unroll
    for (int ck = 0; ck < 4; ck++) {
        if (ck + 1 < 4) {
            load_chunk_k256(c.sb + (uint32_t)((ck + 1) & 1) * CHUNK_BYTES,
                            c.tid, c.m0, c.n0, M, ck + 1, Af, Bf);
            cp_commit();
            cp_wait<1>();
        } else {
            cp_wait<0>();
        }
        __syncthreads();
        mma_chunk(c, c.sb + (uint32_t)(ck & 1) * CHUNK_BYTES, D);
        __syncthreads();
    }

#pragma unroll
    for (int g = 0; g < 4; g++) {
#pragma unroll
        for (int n = 0; n < 4; n++) {
            int r0  = c.m0 + c.wm * 64 + g * 16 + (c.lane >> 2);
            int col = c.n0 + c.wn * 32 + n * 8 + (c.lane & 3) * 2;
            float2 bv = *(const float2*)(bias + col);
            float v0 = D[g][n][0] + bv.x, v1 = D[g][n][1] + bv.y;
            float v2 = D[g][n][2] + bv.x, v3 = D[g][n][3] + bv.y;
            if (EPI == 2) {
                v0 = fmaxf(v0, 0.f); v1 = fmaxf(v1, 0.f);
                v2 = fmaxf(v2, 0.f); v3 = fmaxf(v3, 0.f);
            }
            if (r0 < M)
                *(uint32_t*)(outH + (size_t)r0 * C_DIM + col) = pack_h2(v0, v1);
            if (r0 + 8 < M)
                *(uint32_t*)(outH + (size_t)(r0 + 8) * C_DIM + col) = pack_h2(v2, v3);
        }
    }
}

// ---------------- GEMM B: K=512 fused lin, fp32 out ----------------
// new[M,256] = [A1 | A2] @ WCAT^T + bias.  A chunks 0-3 from A1, 4-7 from A2.
// WCAT K-major [n, 512].
__device__ __forceinline__ void load_chunk_k512(
    uint32_t sbuf, int tid, int m0, int n0, int M, int c,
    const f16* A1, const f16* A2, const f16* Bf)
{
    const f16* ap = (c < 4) ? A1 : A2;
    const int ka = (c & 3) * 64;
    const int kb = c * 64;
#pragma unroll
    for (int i = 0; i < 4; i++) {
        int idx = tid + i * 256;
        int r = idx >> 3, u = idx & 7;
        int rg = min(m0 + r, M - 1);
        uint32_t so = SW128((uint32_t)(r * 128 + u * 16));
        cp16(sbuf + so, (const char*)(ap + (size_t)rg * C_DIM + ka) + u * 16);
    }
#pragma unroll
    for (int i = 0; i < 4; i++) {
        int idx = tid + i * 256;
        int r = idx >> 3, u = idx & 7;
        uint32_t so = SW128((uint32_t)(r * 128 + u * 16));
        cp16(sbuf + 16384 + so, (const char*)(Bf + (size_t)(n0 + r) * 512 + kb) + u * 16);
    }
}

__global__ __launch_bounds__(256, 2)
void gemm_lin(const f16* __restrict__ A1, const f16* __restrict__ A2,
              const f16* __restrict__ Bf, const float* __restrict__ bias,
              float* __restrict__ outF, int M)
{
    extern __shared__ char smem[];
    TileCtx c; tile_init(c);
    c.sb = smem_u32(smem);

    float D[4][4][4];
#pragma unroll
    for (int g = 0; g < 4; g++)
#pragma unroll
        for (int n = 0; n < 4; n++)
#pragma unroll
            for (int q = 0; q < 4; q++) D[g][n][q] = 0.f;

    load_chunk_k512(c.sb, c.tid, c.m0, c.n0, M, 0, A1, A2, Bf);
    cp_commit();

#pragma unroll
    for (int ck = 0; ck < 8; ck++) {
        if (ck + 1 < 8) {
            load_chunk_k512(c.sb + (uint32_t)((ck + 1) & 1) * CHUNK_BYTES,
                            c.tid, c.m0, c.n0, M, ck + 1, A1, A2, Bf);
            cp_commit();
            cp_wait<1>();
        } else {
            cp_wait<0>();
        }
        __syncthreads();
        mma_chunk(c, c.sb + (uint32_t)(ck & 1) * CHUNK_BYTES, D);
        __syncthreads();
    }

#pragma unroll
    for (int g = 0; g < 4; g++) {
#pragma unroll
        for (int n = 0; n < 4; n++) {
            int r0  = c.m0 + c.wm * 64 + g * 16 + (c.lane >> 2);
            int col = c.n0 + c.wn * 32 + n * 8 + (c.lane & 3) * 2;
            float2 bv = *(const float2*)(bias + col);
            if (r0 < M)
                *(float2*)(outF + (size_t)r0 * C_DIM + col) =
                    make_float2(D[g][n][0] + bv.x, D[g][n][1] + bv.y);
            if (r0 + 8 < M)
                *(float2*)(outF + (size_t)(r0 + 8) * C_DIM + col) =
                    make_float2(D[g][n][2] + bv.x, D[g][n][3] + bv.y);
        }
    }
}

// ---------------- aux kernels ----------------
__global__ void f32_to_f16_kernel(const float* __restrict__ x,
                                  f16* __restrict__ out, int n4)
{
    int idx = blockIdx.x * blockDim.x + threadIdx.x;
    if (idx >= n4) return;
    float4 v = ((const float4*)x)[idx];
    *(uint2*)(out + (size_t)idx * 4) = make_uint2(pack_h2(v.x, v.y), pack_h2(v.z, v.w));
}

// One launch converts ALL weights. Per conv t: W1T | W2T | WCATT.
__global__ void convert_all_w_kernel(const float* __restrict__ pw1,
                                     const float* __restrict__ pw2,
                                     const float* __restrict__ lin_w,
                                     f16* __restrict__ out)
{
    int idx = blockIdx.x * blockDim.x + threadIdx.x;
    if (idx >= 4 * WSTRIDE) return;
    int t   = idx >> 18;
    int rem = idx & (WSTRIDE - 1);
    float v;
    if (rem < 65536) {                   // W1T: dst[n*256+k]
        int n = rem >> 8, k = rem & 255;
        v = pw1[(size_t)t * 65536 + k * 256 + n];
    } else if (rem < 131072) {           // W2T
        int e = rem - 65536;
        int n = e >> 8, k = e & 255;
        v = pw2[(size_t)t * 65536 + k * 256 + n];
    } else {                             // WCATT: dst[n*512+k], lin_w [512,256] row-major
        int e = rem - 131072;
        int n = e >> 9, k = e & 511;
        v = lin_w[(size_t)t * 131072 + (size_t)k * 256 + n];
    }
    out[idx] = __float2half_rn(v);
}

__global__ void count_kernel(const int* __restrict__ dst, float* __restrict__ cnt, int nE)
{
    int i = blockIdx.x * blockDim.x + threadIdx.x;
    if (i < nE) atomicAdd(cnt + __ldg(dst + i), 1.0f);
}

// fp16 edge stage: msg = LN(x_src[s] - P[d]) * g + b, red into fp32 agg
__global__ void edge_msg_kernel(const f16* __restrict__ xsrc,
                                const f16* __restrict__ Pn,
                                const int* __restrict__ ei,
                                const float* __restrict__ gg,
                                const float* __restrict__ bb,
                                float* __restrict__ agg, int nE)
{
    int w = (blockIdx.x * blockDim.x + threadIdx.x) >> 5;
    int lane = threadIdx.x & 31;
    if (w >= nE) return;
    int s = __ldg(ei + w);
    int d = __ldg(ei + nE + w);
    int c0 = lane << 3;

    uint4 xv = *(const uint4*)(xsrc + (size_t)s * C_DIM + c0);
    uint4 pv = *(const uint4*)(Pn   + (size_t)d * C_DIM + c0);
    const __half2* xh = (const __half2*)&xv;
    const __half2* ph = (const __half2*)&pv;
    float r[8];
#pragma unroll
    for (int i = 0; i < 4; i++) {
        float2 xf = __half22float2(xh[i]);
        float2 pf = __half22float2(ph[i]);
        r[i * 2]     = xf.x - pf.x;
        r[i * 2 + 1] = xf.y - pf.y;
    }
    float s1 = 0.f;
#pragma unroll
    for (int i = 0; i < 8; i++) s1 += r[i];
    float mean = warp_sum(s1) * (1.f / 256.f);
    float s2 = 0.f;
#pragma unroll
    for (int i = 0; i < 8; i++) { float t = r[i] - mean; s2 += t * t; }
    float inv = rsqrtf(warp_sum(s2) * (1.f / 256.f) + EPS_LN);
    float4 g0 = *(const float4*)(gg + c0), g1 = *(const float4*)(gg + c0 + 4);
    float4 e0 = *(const float4*)(bb + c0), e1 = *(const float4*)(bb + c0 + 4);
    float m0v = (r[0] - mean) * inv * g0.x + e0.x;
    float m1v = (r[1] - mean) * inv * g0.y + e0.y;
    float m2v = (r[2] - mean) * inv * g0.z + e0.z;
    float m3v = (r[3] - mean) * inv * g0.w + e0.w;
    float m4v = (r[4] - mean) * inv * g1.x + e1.x;
    float m5v = (r[5] - mean) * inv * g1.y + e1.y;
    float m6v = (r[6] - mean) * inv * g1.z + e1.z;
    float m7v = (r[7] - mean) * inv * g1.w + e1.w;
    float* dstp = agg + (size_t)d * C_DIM + c0;
    asm volatile("red.global.add.v4.f32 [%0], {%1,%2,%3,%4};"
                 :: "l"(dstp), "f"(m0v), "f"(m1v), "f"(m2v), "f"(m3v) : "memory");
    asm volatile("red.global.add.v4.f32 [%0], {%1,%2,%3,%4};"
                 :: "l"(dstp + 4), "f"(m4v), "f"(m5v), "f"(m6v), "f"(m7v) : "memory");
}

// agg/max(cnt,1) -> fp16 (read-only on agg; memset handles zeroing)
__global__ void norm_agg_f16_kernel(const float* __restrict__ agg,
                                    const float* __restrict__ cnt,
                                    f16* __restrict__ out, int n)
{
    int idx = blockIdx.x * blockDim.x + threadIdx.x;
    if (idx >= n * 64) return;
    int row = idx >> 6;
    float inv = 1.f / fmaxf(__ldg(cnt + row), 1.f);
    float4 v = ((const float4*)agg)[idx];
    *(uint2*)(out + (size_t)idx * 4) =
        make_uint2(pack_h2(v.x * inv, v.y * inv), pack_h2(v.z * inv, v.w * inv));
}

// out = relu(LN(X)*g+b); fp32 out (nullable), fp16 out (nullable)
__global__ void node_ln_relu_kernel(const float* __restrict__ X,
                                    const float* __restrict__ gg, const float* __restrict__ bb,
                                    float* __restrict__ out, f16* __restrict__ outh, int M)
{
    int w = (blockIdx.x * blockDim.x + threadIdx.x) >> 5;
    int lane = threadIdx.x & 31;
    if (w >= M) return;
    int c0 = lane << 3;
    const float4* xp = (const float4*)(X + (size_t)w * C_DIM + c0);
    float4 a0 = xp[0], a1 = xp[1];
    float r[8] = {a0.x, a0.y, a0.z, a0.w, a1.x, a1.y, a1.z, a1.w};
    float s1 = 0.f;
#pragma unroll
    for (int i = 0; i < 8; i++) s1 += r[i];
    float mean = warp_sum(s1) * (1.f / 256.f);
    float s2 = 0.f;
#pragma unroll
    for (int i = 0; i < 8; i++) { float t = r[i] - mean; s2 += t * t; }
    float inv = rsqrtf(warp_sum(s2) * (1.f / 256.f) + EPS_LN);
    float4 g0 = *(const float4*)(gg + c0), g1 = *(const float4*)(gg + c0 + 4);
    float4 e0 = *(const float4*)(bb + c0), e1 = *(const float4*)(bb + c0 + 4);
    float o[8];
    o[0] = fmaxf((r[0] - mean) * inv * g0.x + e0.x, 0.f);
    o[1] = fmaxf((r[1] - mean) * inv * g0.y + e0.y, 0.f);
    o[2] = fmaxf((r[2] - mean) * inv * g0.z + e0.z, 0.f);
    o[3] = fmaxf((r[3] - mean) * inv * g0.w + e0.w, 0.f);
    o[4] = fmaxf((r[4] - mean) * inv * g1.x + e1.x, 0.f);
    o[5] = fmaxf((r[5] - mean) * inv * g1.y + e1.y, 0.f);
    o[6] = fmaxf((r[6] - mean) * inv * g1.z + e1.z, 0.f);
    o[7] = fmaxf((r[7] - mean) * inv * g1.w + e1.w, 0.f);
    if (out) {
        float4* op = (float4*)(out + (size_t)w * C_DIM + c0);
        op[0] = make_float4(o[0], o[1], o[2], o[3]);
        op[1] = make_float4(o[4], o[5], o[6], o[7]);
    }
    if (outh) {
        *(uint4*)(outh + (size_t)w * C_DIM + c0) =
            make_uint4(pack_h2(o[0], o[1]), pack_h2(o[2], o[3]),
                       pack_h2(o[4], o[5]), pack_h2(o[6], o[7]));
    }
}

// ---------------- host ----------------
extern "C" void kernel_launch(void* const* d_in, const int* in_sizes, int n_in,
                              void* d_out, int out_size)
{
    const float* x_user = (const float*)d_in[0];
    const float* x_item = (const float*)d_in[1];
    const float* pw1    = (const float*)d_in[2];
    const float* pb1    = (const float*)d_in[3];
    const float* pw2    = (const float*)d_in[4];
    const float* pb2    = (const float*)d_in[5];
    const float* msg_g  = (const float*)d_in[6];
    const float* msg_b  = (const float*)d_in[7];
    const float* lin_w  = (const float*)d_in[8];
    const float* lin_b  = (const float*)d_in[9];
    const float* node_g = (const float*)d_in[10];
    const float* node_b = (const float*)d_in[11];
    const int*   ei_ui  = (const int*)d_in[12];
    const int*   ei_iu  = (const int*)d_in[13];

    const int NUn = in_sizes[0] / C_DIM;
    const int NIn = in_sizes[1] / C_DIM;
    const int nE0 = in_sizes[12] / 2;
    const int nE1 = in_sizes[13] / 2;
    const int Lm = 2;

    float *aggb, *new_u, *new_i, *cnt_i, *cnt_u;
    f16 *xu_f, *xi_f, *h_f, *a_f, *p_f, *w_f;
    cudaGetSymbolAddress((void**)&aggb, g_agg);
    cudaGetSymbolAddress((void**)&new_u, g_new_u);
    cudaGetSymbolAddress((void**)&new_i, g_new_i);
    cudaGetSymbolAddress((void**)&cnt_i, g_cnt_i);
    cudaGetSymbolAddress((void**)&cnt_u, g_cnt_u);
    cudaGetSymbolAddress((void**)&xu_f, g_xu_f);
    cudaGetSymbolAddress((void**)&xi_f, g_xi_f);
    cudaGetSymbolAddress((void**)&h_f, g_h_f);
    cudaGetSymbolAddress((void**)&a_f, g_a_f);
    cudaGetSymbolAddress((void**)&p_f, g_p_f);
    cudaGetSymbolAddress((void**)&w_f, g_w);

    cudaFuncSetAttribute(gemm_h<0>, cudaFuncAttributeMaxDynamicSharedMemorySize, GEMM_SMEM);
    cudaFuncSetAttribute(gemm_h<2>, cudaFuncAttributeMaxDynamicSharedMemorySize, GEMM_SMEM);
    cudaFuncSetAttribute(gemm_lin, cudaFuncAttributeMaxDynamicSharedMemorySize, GEMM_SMEM);

    convert_all_w_kernel<<<(4 * WSTRIDE + 255) / 256, 256>>>(pw1, pw2, lin_w, w_f);
    f32_to_f16_kernel<<<(NUn * 64 + 255) / 256, 256>>>(x_user, xu_f, NUn * 64);
    f32_to_f16_kernel<<<(NIn * 64 + 255) / 256, 256>>>(x_item, xi_f, NIn * 64);

    cudaMemsetAsync(cnt_i, 0, (size_t)NIn * sizeof(float));
    cudaMemsetAsync(cnt_u, 0, (size_t)NUn * sizeof(float));
    count_kernel<<<(nE0 + 255) / 256, 256>>>(ei_ui + nE0, cnt_i, nE0);
    count_kernel<<<(nE1 + 255) / 256, 256>>>(ei_iu + nE1, cnt_u, nE1);

    float* out_f = (float*)d_out;

    for (int l = 0; l < Lm; l++) {
        bool last = (l == Lm - 1);
        // ---- conv: dst = item, src = user (params [l,0]) ----
        {
            int t = l * 2 + 0;
            size_t wo = (size_t)t * WSTRIDE;
            dim3 g2((NIn + 127) / 128, 2);
            gemm_h<2><<<g2, 256, GEMM_SMEM>>>(xi_f, w_f + wo,
                pb1 + (size_t)t * C_DIM, h_f, NIn);
            gemm_h<0><<<g2, 256, GEMM_SMEM>>>(h_f, w_f + wo + 65536,
                pb2 + (size_t)t * C_DIM, p_f, NIn);
            // memset directly before edge kernel keeps agg resident in L2 for the atomics
            cudaMemsetAsync(aggb, 0, (size_t)NIn * C_DIM * sizeof(float));
            edge_msg_kernel<<<(nE0 * 32 + 255) / 256, 256>>>(xu_f, p_f, ei_ui,
                msg_g + (size_t)t * C_DIM, msg_b + (size_t)t * C_DIM, aggb, nE0);
            norm_agg_f16_kernel<<<(NIn * 64 + 255) / 256, 256>>>(aggb, cnt_i, a_f, NIn);
            gemm_lin<<<g2, 256, GEMM_SMEM>>>(xi_f, a_f, w_f + wo + 131072,
                lin_b + (size_t)t * C_DIM, new_i, NIn);
        }
        // ---- conv: dst = user, src = item (params [l,1]) ----
        {
            int t = l * 2 + 1;
            size_t wo = (size_t)t * WSTRIDE;
            dim3 g2((NUn + 127) / 128, 2);
            gemm_h<2><<<g2, 256, GEMM_SMEM>>>(xu_f, w_f + wo,
                pb1 + (size_t)t * C_DIM, h_f, NUn);
            gemm_h<0><<<g2, 256, GEMM_SMEM>>>(h_f, w_f + wo + 65536,
                pb2 + (size_t)t * C_DIM, p_f, NUn);
            cudaMemsetAsync(aggb, 0, (size_t)NUn * C_DIM * sizeof(float));
            edge_msg_kernel<<<(nE1 * 32 + 255) / 256, 256>>>(xi_f, p_f, ei_iu,
                msg_g + (size_t)t * C_DIM, msg_b + (size_t)t * C_DIM, aggb, nE1);
            norm_agg_f16_kernel<<<(NUn * 64 + 255) / 256, 256>>>(aggb, cnt_u, a_f, NUn);
            gemm_lin<<<g2, 256, GEMM_SMEM>>>(xu_f, a_f, w_f + wo + 131072,
                lin_b + (size_t)t * C_DIM, new_u, NUn);
        }
        // ---- node LN + relu ----
        node_ln_relu_kernel<<<(NUn * 32 + 255) / 256, 256>>>(new_u,
            node_g + (size_t)(l * 2 + 0) * C_DIM, node_b + (size_t)(l * 2 + 0) * C_DIM,
            last ? out_f : (float*)0, last ? (f16*)0 : xu_f, NUn);
        node_ln_relu_kernel<<<(NIn * 32 + 255) / 256, 256>>>(new_i,
            node_g + (size_t)(l * 2 + 1) * C_DIM, node_b + (size_t)(l * 2 + 1) * C_DIM,
            last ? (out_f + (size_t)NUn * C_DIM) : (float*)0, last ? (f16*)0 : xi_f, NIn);
    }
    (void)n_in; (void)out_size;
}

// round 17
// speedup vs baseline: 1.8211x; 1.0246x over previous
#include <cuda_runtime.h>
#include <cuda_fp16.h>
#include <cstdint>

#define C_DIM   256
#define MAXN    100000
#define EPS_LN  1e-5f

typedef __half f16;

// ---------------- device scratch ----------------
__device__ float g_agg  [MAXN * C_DIM];
__device__ float g_cnt_i[MAXN];
__device__ float g_cnt_u[MAXN];

__device__ __align__(16) f16 g_xu_f[MAXN * C_DIM];
__device__ __align__(16) f16 g_xi_f[MAXN * C_DIM];
__device__ __align__(16) f16 g_h_f [MAXN * C_DIM];
__device__ __align__(16) f16 g_a_f [MAXN * C_DIM];
__device__ __align__(16) f16 g_p_f [MAXN * C_DIM];
__device__ __align__(16) f16 g_nu_f[MAXN * C_DIM];   // new_u (f16)
__device__ __align__(16) f16 g_ni_f[MAXN * C_DIM];   // new_i (f16)

// per conv: W1T[256,256] | W2T[256,256] | WCATT[256,512]
// W1T/W2T: dst[n*256+k]; WCATT: dst[n*512+k] with k<256 = Wx, k>=256 = Wa
#define WSTRIDE (262144)
__device__ __align__(16) f16 g_w[4 * WSTRIDE];

// ---------------- helpers ----------------
__device__ __forceinline__ uint32_t smem_u32(const void* p) {
    uint32_t a;
    asm("{ .reg .u64 t; cvta.to.shared.u64 t, %1; cvt.u32.u64 %0, t; }" : "=r"(a) : "l"(p));
    return a;
}
__device__ __forceinline__ void cp16(uint32_t s, const void* g) {
    asm volatile("cp.async.cg.shared.global [%0], [%1], 16;" :: "r"(s), "l"(g));
}
__device__ __forceinline__ void cp_commit() { asm volatile("cp.async.commit_group;" ::: "memory"); }
template<int N> __device__ __forceinline__ void cp_wait() {
    asm volatile("cp.async.wait_group %0;" :: "n"(N) : "memory");
}
#define SW128(o) ((o) ^ (((o) >> 3) & 0x70))

__device__ __forceinline__ uint32_t pack_h2(float a, float b) {
    __half2 t = __halves2half2(__float2half_rn(a), __float2half_rn(b));
    return *reinterpret_cast<uint32_t*>(&t);
}

#define LDSM4(r0, r1, r2, r3, addr) \
    asm volatile("ldmatrix.sync.aligned.m8n8.x4.shared.b16 {%0,%1,%2,%3}, [%4];" \
                 : "=r"(r0), "=r"(r1), "=r"(r2), "=r"(r3) : "r"(addr))

#define MMA16816F(d, a, b0, b1) \
    asm volatile("mma.sync.aligned.m16n8k16.row.col.f32.f16.f16.f32 " \
                 "{%0,%1,%2,%3}, {%4,%5,%6,%7}, {%8,%9}, {%0,%1,%2,%3};" \
                 : "+f"((d)[0]), "+f"((d)[1]), "+f"((d)[2]), "+f"((d)[3]) \
                 : "r"((a)[0]), "r"((a)[1]), "r"((a)[2]), "r"((a)[3]), \
                   "r"(b0), "r"(b1))

__device__ __forceinline__ float warp_sum(float v) {
#pragma unroll
    for (int o = 16; o > 0; o >>= 1) v += __shfl_xor_sync(0xffffffffu, v, o);
    return v;
}

#define CHUNK_BYTES 32768
#define GEMM_SMEM   (2 * CHUNK_BYTES)

// ---------------- mainloop core ----------------
struct TileCtx {
    uint32_t sb, aOff, bOff;
    int tid, lane, wid, wm, wn, m0, n0;
};

__device__ __forceinline__ void tile_init(TileCtx& c) {
    c.tid  = threadIdx.x;
    c.lane = c.tid & 31;
    c.wid  = c.tid >> 5;
    c.wm   = c.wid >> 2;
    c.wn   = c.wid & 3;
    c.m0   = blockIdx.x * 128;
    c.n0   = blockIdx.y * 128;
    c.aOff = (uint32_t)((c.wm * 64 + (c.lane & 15)) * 128 + ((c.lane >> 4) << 4));
    c.bOff = (uint32_t)((c.wn * 32 + (c.lane & 7) + ((c.lane >> 4) << 3)) * 128
                        + (((c.lane >> 3) & 1) << 4));
}

__device__ __forceinline__ void mma_chunk(const TileCtx& c, uint32_t base, float D[4][4][4]) {
#pragma unroll
    for (int ks = 0; ks < 4; ks++) {
        const uint32_t kb = (uint32_t)(ks * 32);
        uint32_t af[4][4];
#pragma unroll
        for (int g = 0; g < 4; g++) {
            uint32_t sw = SW128(c.aOff + (uint32_t)(g * 2048) + kb);
            LDSM4(af[g][0], af[g][1], af[g][2], af[g][3], base + sw);
        }
        uint32_t bh[2][4];
#pragma unroll
        for (int p = 0; p < 2; p++) {
            uint32_t sw = SW128(c.bOff + (uint32_t)(p * 2048) + kb);
            LDSM4(bh[p][0], bh[p][1], bh[p][2], bh[p][3], base + 16384 + sw);
        }
#pragma unroll
        for (int g = 0; g < 4; g++) {
#pragma unroll
            for (int n = 0; n < 4; n++) {
                const int p = n >> 1, rb = (n & 1) * 2;
                MMA16816F(D[g][n], af[g], bh[p][rb], bh[p][rb + 1]);
            }
        }
    }
}

// ---------------- GEMM A: K=256, f16 out (optional relu) ----------------
__device__ __forceinline__ void load_chunk_k256(
    uint32_t sbuf, int tid, int m0, int n0, int M, int c,
    const f16* Af, const f16* Bf)
{
    const int k0 = c * 64;
#pragma unroll
    for (int i = 0; i < 4; i++) {
        int idx = tid + i * 256;
        int r = idx >> 3, u = idx & 7;
        int rg = min(m0 + r, M - 1);
        uint32_t so = SW128((uint32_t)(r * 128 + u * 16));
        cp16(sbuf + so, (const char*)(Af + (size_t)rg * C_DIM + k0) + u * 16);
    }
#pragma unroll
    for (int i = 0; i < 4; i++) {
        int idx = tid + i * 256;
        int r = idx >> 3, u = idx & 7;
        uint32_t so = SW128((uint32_t)(r * 128 + u * 16));
        cp16(sbuf + 16384 + so, (const char*)(Bf + (size_t)(n0 + r) * C_DIM + k0) + u * 16);
    }
}

template<int RELU>
__global__ __launch_bounds__(256, 2)
void gemm_h(const f16* __restrict__ Af, const f16* __restrict__ Bf,
            const float* __restrict__ bias, f16* __restrict__ outH, int M)
{
    extern __shared__ char smem[];
    TileCtx c; tile_init(c);
    c.sb = smem_u32(smem);

    float D[4][4][4];
#pragma unroll
    for (int g = 0; g < 4; g++)
#pragma unroll
        for (int n = 0; n < 4; n++)
#pragma unroll
            for (int q = 0; q < 4; q++) D[g][n][q] = 0.f;

    load_chunk_k256(c.sb, c.tid, c.m0, c.n0, M, 0, Af, Bf);
    cp_commit();

#pragma unroll
    for (int ck = 0; ck < 4; ck++) {
        if (ck + 1 < 4) {
            load_chunk_k256(c.sb + (uint32_t)((ck + 1) & 1) * CHUNK_BYTES,
                            c.tid, c.m0, c.n0, M, ck + 1, Af, Bf);
            cp_commit();
            cp_wait<1>();
        } else {
            cp_wait<0>();
        }
        __syncthreads();
        mma_chunk(c, c.sb + (uint32_t)(ck & 1) * CHUNK_BYTES, D);
        __syncthreads();
    }

#pragma unroll
    for (int g = 0; g < 4; g++) {
#pragma unroll
        for (int n = 0; n < 4; n++) {
            int r0  = c.m0 + c.wm * 64 + g * 16 + (c.lane >> 2);
            int col = c.n0 + c.wn * 32 + n * 8 + (c.lane & 3) * 2;
            float2 bv = *(const float2*)(bias + col);
            float v0 = D[g][n][0] + bv.x, v1 = D[g][n][1] + bv.y;
            float v2 = D[g][n][2] + bv.x, v3 = D[g][n][3] + bv.y;
            if (RELU) {
                v0 = fmaxf(v0, 0.f); v1 = fmaxf(v1, 0.f);
                v2 = fmaxf(v2, 0.f); v3 = fmaxf(v3, 0.f);
            }
            if (r0 < M)
                *(uint32_t*)(outH + (size_t)r0 * C_DIM + col) = pack_h2(v0, v1);
            if (r0 + 8 < M)
                *(uint32_t*)(outH + (size_t)(r0 + 8) * C_DIM + col) = pack_h2(v2, v3);
        }
    }
}

// ---------------- GEMM B: K=512 fused lin, f16 out ----------------
// new[M,256] = f16([A1 | A2] @ WCAT^T + bias). A chunks 0-3 from A1, 4-7 from A2.
__device__ __forceinline__ void load_chunk_k512(
    uint32_t sbuf, int tid, int m0, int n0, int M, int c,
    const f16* A1, const f16* A2, const f16* Bf)
{
    const f16* ap = (c < 4) ? A1 : A2;
    const int ka = (c & 3) * 64;
    const int kb = c * 64;
#pragma unroll
    for (int i = 0; i < 4; i++) {
        int idx = tid + i * 256;
        int r = idx >> 3, u = idx & 7;
        int rg = min(m0 + r, M - 1);
        uint32_t so = SW128((uint32_t)(r * 128 + u * 16));
        cp16(sbuf + so, (const char*)(ap + (size_t)rg * C_DIM + ka) + u * 16);
    }
#pragma unroll
    for (int i = 0; i < 4; i++) {
        int idx = tid + i * 256;
        int r = idx >> 3, u = idx & 7;
        uint32_t so = SW128((uint32_t)(r * 128 + u * 16));
        cp16(sbuf + 16384 + so, (const char*)(Bf + (size_t)(n0 + r) * 512 + kb) + u * 16);
    }
}

__global__ __launch_bounds__(256, 2)
void gemm_lin(const f16* __restrict__ A1, const f16* __restrict__ A2,
              const f16* __restrict__ Bf, const float* __restrict__ bias,
              f16* __restrict__ outH, int M)
{
    extern __shared__ char smem[];
    TileCtx c; tile_init(c);
    c.sb = smem_u32(smem);

    float D[4][4][4];
#pragma unroll
    for (int g = 0; g < 4; g++)
#pragma unroll
        for (int n = 0; n < 4; n++)
#pragma unroll
            for (int q = 0; q < 4; q++) D[g][n][q] = 0.f;

    load_chunk_k512(c.sb, c.tid, c.m0, c.n0, M, 0, A1, A2, Bf);
    cp_commit();

#pragma unroll
    for (int ck = 0; ck < 8; ck++) {
        if (ck + 1 < 8) {
            load_chunk_k512(c.sb + (uint32_t)((ck + 1) & 1) * CHUNK_BYTES,
                            c.tid, c.m0, c.n0, M, ck + 1, A1, A2, Bf);
            cp_commit();
            cp_wait<1>();
        } else {
            cp_wait<0>();
        }
        __syncthreads();
        mma_chunk(c, c.sb + (uint32_t)(ck & 1) * CHUNK_BYTES, D);
        __syncthreads();
    }

#pragma unroll
    for (int g = 0; g < 4; g++) {
#pragma unroll
        for (int n = 0; n < 4; n++) {
            int r0  = c.m0 + c.wm * 64 + g * 16 + (c.lane >> 2);
            int col = c.n0 + c.wn * 32 + n * 8 + (c.lane & 3) * 2;
            float2 bv = *(const float2*)(bias + col);
            if (r0 < M)
                *(uint32_t*)(outH + (size_t)r0 * C_DIM + col) =
                    pack_h2(D[g][n][0] + bv.x, D[g][n][1] + bv.y);
            if (r0 + 8 < M)
                *(uint32_t*)(outH + (size_t)(r0 + 8) * C_DIM + col) =
                    pack_h2(D[g][n][2] + bv.x, D[g][n][3] + bv.y);
        }
    }
}

// ---------------- aux kernels ----------------
__global__ void f32_to_f16_kernel(const float* __restrict__ x,
                                  f16* __restrict__ out, int n4)
{
    int idx = blockIdx.x * blockDim.x + threadIdx.x;
    if (idx >= n4) return;
    float4 v = ((const float4*)x)[idx];
    *(uint2*)(out + (size_t)idx * 4) = make_uint2(pack_h2(v.x, v.y), pack_h2(v.z, v.w));
}

// One launch converts ALL weights. Per conv t: W1T | W2T | WCATT.
__global__ void convert_all_w_kernel(const float* __restrict__ pw1,
                                     const float* __restrict__ pw2,
                                     const float* __restrict__ lin_w,
                                     f16* __restrict__ out)
{
    int idx = blockIdx.x * blockDim.x + threadIdx.x;
    if (idx >= 4 * WSTRIDE) return;
    int t   = idx >> 18;
    int rem = idx & (WSTRIDE - 1);
    float v;
    if (rem < 65536) {                   // W1T: dst[n*256+k]
        int n = rem >> 8, k = rem & 255;
        v = pw1[(size_t)t * 65536 + k * 256 + n];
    } else if (rem < 131072) {           // W2T
        int e = rem - 65536;
        int n = e >> 8, k = e & 255;
        v = pw2[(size_t)t * 65536 + k * 256 + n];
    } else {                             // WCATT: dst[n*512+k], lin_w [512,256] row-major
        int e = rem - 131072;
        int n = e >> 9, k = e & 511;
        v = lin_w[(size_t)t * 131072 + (size_t)k * 256 + n];
    }
    out[idx] = __float2half_rn(v);
}

__global__ void count_kernel(const int* __restrict__ dst, float* __restrict__ cnt, int nE)
{
    int i = blockIdx.x * blockDim.x + threadIdx.x;
    if (i < nE) atomicAdd(cnt + __ldg(dst + i), 1.0f);
}

// fp16 edge stage: msg = LN(x_src[s] - P[d]) * g + b, red into fp32 agg
__global__ void edge_msg_kernel(const f16* __restrict__ xsrc,
                                const f16* __restrict__ Pn,
                                const int* __restrict__ ei,
                                const float* __restrict__ gg,
                                const float* __restrict__ bb,
                                float* __restrict__ agg, int nE)
{
    int w = (blockIdx.x * blockDim.x + threadIdx.x) >> 5;
    int lane = threadIdx.x & 31;
    if (w >= nE) return;
    int s = __ldg(ei + w);
    int d = __ldg(ei + nE + w);
    int c0 = lane << 3;

    uint4 xv = *(const uint4*)(xsrc + (size_t)s * C_DIM + c0);
    uint4 pv = *(const uint4*)(Pn   + (size_t)d * C_DIM + c0);
    const __half2* xh = (const __half2*)&xv;
    const __half2* ph = (const __half2*)&pv;
    float r[8];
#pragma unroll
    for (int i = 0; i < 4; i++) {
        float2 xf = __half22float2(xh[i]);
        float2 pf = __half22float2(ph[i]);
        r[i * 2]     = xf.x - pf.x;
        r[i * 2 + 1] = xf.y - pf.y;
    }
    float s1 = 0.f;
#pragma unroll
    for (int i = 0; i < 8; i++) s1 += r[i];
    float mean = warp_sum(s1) * (1.f / 256.f);
    float s2 = 0.f;
#pragma unroll
    for (int i = 0; i < 8; i++) { float t = r[i] - mean; s2 += t * t; }
    float inv = rsqrtf(warp_sum(s2) * (1.f / 256.f) + EPS_LN);
    float4 g0 = *(const float4*)(gg + c0), g1 = *(const float4*)(gg + c0 + 4);
    float4 e0 = *(const float4*)(bb + c0), e1 = *(const float4*)(bb + c0 + 4);
    float m0v = (r[0] - mean) * inv * g0.x + e0.x;
    float m1v = (r[1] - mean) * inv * g0.y + e0.y;
    float m2v = (r[2] - mean) * inv * g0.z + e0.z;
    float m3v = (r[3] - mean) * inv * g0.w + e0.w;
    float m4v = (r[4] - mean) * inv * g1.x + e1.x;
    float m5v = (r[5] - mean) * inv * g1.y + e1.y;
    float m6v = (r[6] - mean) * inv * g1.z + e1.z;
    float m7v = (r[7] - mean) * inv * g1.w + e1.w;
    float* dstp = agg + (size_t)d * C_DIM + c0;
    asm volatile("red.global.add.v4.f32 [%0], {%1,%2,%3,%4};"
                 :: "l"(dstp), "f"(m0v), "f"(m1v), "f"(m2v), "f"(m3v) : "memory");
    asm volatile("red.global.add.v4.f32 [%0], {%1,%2,%3,%4};"
                 :: "l"(dstp + 4), "f"(m4v), "f"(m5v), "f"(m6v), "f"(m7v) : "memory");
}

// agg/max(cnt,1) -> fp16 (read-only on agg; memset handles zeroing)
__global__ void norm_agg_f16_kernel(const float* __restrict__ agg,
                                    const float* __restrict__ cnt,
                                    f16* __restrict__ out, int n)
{
    int idx = blockIdx.x * blockDim.x + threadIdx.x;
    if (idx >= n * 64) return;
    int row = idx >> 6;
    float inv = 1.f / fmaxf(__ldg(cnt + row), 1.f);
    float4 v = ((const float4*)agg)[idx];
    *(uint2*)(out + (size_t)idx * 4) =
        make_uint2(pack_h2(v.x * inv, v.y * inv), pack_h2(v.z * inv, v.w * inv));
}

// out = relu(LN(X_f16)*g+b); fp32 out (nullable), fp16 out (nullable)
__global__ void node_ln_relu_kernel(const f16* __restrict__ X,
                                    const float* __restrict__ gg, const float* __restrict__ bb,
                                    float* __restrict__ out, f16* __restrict__ outh, int M)
{
    int w = (blockIdx.x * blockDim.x + threadIdx.x) >> 5;
    int lane = threadIdx.x & 31;
    if (w >= M) return;
    int c0 = lane << 3;
    uint4 xv = *(const uint4*)(X + (size_t)w * C_DIM + c0);
    const __half2* xh = (const __half2*)&xv;
    float r[8];
#pragma unroll
    for (int i = 0; i < 4; i++) {
        float2 xf = __half22float2(xh[i]);
        r[i * 2]     = xf.x;
        r[i * 2 + 1] = xf.y;
    }
    float s1 = 0.f;
#pragma unroll
    for (int i = 0; i < 8; i++) s1 += r[i];
    float mean = warp_sum(s1) * (1.f / 256.f);
    float s2 = 0.f;
#pragma unroll
    for (int i = 0; i < 8; i++) { float t = r[i] - mean; s2 += t * t; }
    float inv = rsqrtf(warp_sum(s2) * (1.f / 256.f) + EPS_LN);
    float4 g0 = *(const float4*)(gg + c0), g1 = *(const float4*)(gg + c0 + 4);
    float4 e0 = *(const float4*)(bb + c0), e1 = *(const float4*)(bb + c0 + 4);
    float o[8];
    o[0] = fmaxf((r[0] - mean) * inv * g0.x + e0.x, 0.f);
    o[1] = fmaxf((r[1] - mean) * inv * g0.y + e0.y, 0.f);
    o[2] = fmaxf((r[2] - mean) * inv * g0.z + e0.z, 0.f);
    o[3] = fmaxf((r[3] - mean) * inv * g0.w + e0.w, 0.f);
    o[4] = fmaxf((r[4] - mean) * inv * g1.x + e1.x, 0.f);
    o[5] = fmaxf((r[5] - mean) * inv * g1.y + e1.y, 0.f);
    o[6] = fmaxf((r[6] - mean) * inv * g1.z + e1.z, 0.f);
    o[7] = fmaxf((r[7] - mean) * inv * g1.w + e1.w, 0.f);
    if (out) {
        float4* op = (float4*)(out + (size_t)w * C_DIM + c0);
        op[0] = make_float4(o[0], o[1], o[2], o[3]);
        op[1] = make_float4(o[4], o[5], o[6], o[7]);
    }
    if (outh) {
        *(uint4*)(outh + (size_t)w * C_DIM + c0) =
            make_uint4(pack_h2(o[0], o[1]), pack_h2(o[2], o[3]),
                       pack_h2(o[4], o[5]), pack_h2(o[6], o[7]));
    }
}

// ---------------- host ----------------
extern "C" void kernel_launch(void* const* d_in, const int* in_sizes, int n_in,
                              void* d_out, int out_size)
{
    const float* x_user = (const float*)d_in[0];
    const float* x_item = (const float*)d_in[1];
    const float* pw1    = (const float*)d_in[2];
    const float* pb1    = (const float*)d_in[3];
    const float* pw2    = (const float*)d_in[4];
    const float* pb2    = (const float*)d_in[5];
    const float* msg_g  = (const float*)d_in[6];
    const float* msg_b  = (const float*)d_in[7];
    const float* lin_w  = (const float*)d_in[8];
    const float* lin_b  = (const float*)d_in[9];
    const float* node_g = (const float*)d_in[10];
    const float* node_b = (const float*)d_in[11];
    const int*   ei_ui  = (const int*)d_in[12];
    const int*   ei_iu  = (const int*)d_in[13];

    const int NUn = in_sizes[0] / C_DIM;
    const int NIn = in_sizes[1] / C_DIM;
    const int nE0 = in_sizes[12] / 2;
    const int nE1 = in_sizes[13] / 2;
    const int Lm = 2;

    float *aggb, *cnt_i, *cnt_u;
    f16 *xu_f, *xi_f, *h_f, *a_f, *p_f, *nu_f, *ni_f, *w_f;
    cudaGetSymbolAddress((void**)&aggb, g_agg);
    cudaGetSymbolAddress((void**)&cnt_i, g_cnt_i);
    cudaGetSymbolAddress((void**)&cnt_u, g_cnt_u);
    cudaGetSymbolAddress((void**)&xu_f, g_xu_f);
    cudaGetSymbolAddress((void**)&xi_f, g_xi_f);
    cudaGetSymbolAddress((void**)&h_f, g_h_f);
    cudaGetSymbolAddress((void**)&a_f, g_a_f);
    cudaGetSymbolAddress((void**)&p_f, g_p_f);
    cudaGetSymbolAddress((void**)&nu_f, g_nu_f);
    cudaGetSymbolAddress((void**)&ni_f, g_ni_f);
    cudaGetSymbolAddress((void**)&w_f, g_w);

    cudaFuncSetAttribute(gemm_h<0>, cudaFuncAttributeMaxDynamicSharedMemorySize, GEMM_SMEM);
    cudaFuncSetAttribute(gemm_h<1>, cudaFuncAttributeMaxDynamicSharedMemorySize, GEMM_SMEM);
    cudaFuncSetAttribute(gemm_lin, cudaFuncAttributeMaxDynamicSharedMemorySize, GEMM_SMEM);

    convert_all_w_kernel<<<(4 * WSTRIDE + 255) / 256, 256>>>(pw1, pw2, lin_w, w_f);
    f32_to_f16_kernel<<<(NUn * 64 + 255) / 256, 256>>>(x_user, xu_f, NUn * 64);
    f32_to_f16_kernel<<<(NIn * 64 + 255) / 256, 256>>>(x_item, xi_f, NIn * 64);

    cudaMemsetAsync(cnt_i, 0, (size_t)NIn * sizeof(float));
    cudaMemsetAsync(cnt_u, 0, (size_t)NUn * sizeof(float));
    count_kernel<<<(nE0 + 255) / 256, 256>>>(ei_ui + nE0, cnt_i, nE0);
    count_kernel<<<(nE1 + 255) / 256, 256>>>(ei_iu + nE1, cnt_u, nE1);

    float* out_f = (float*)d_out;

    for (int l = 0; l < Lm; l++) {
        bool last = (l == Lm - 1);
        // ---- conv: dst = item, src = user (params [l,0]) ----
        {
            int t = l * 2 + 0;
            size_t wo = (size_t)t * WSTRIDE;
            dim3 g2((NIn + 127) / 128, 2);
            gemm_h<1><<<g2, 256, GEMM_SMEM>>>(xi_f, w_f + wo,
                pb1 + (size_t)t * C_DIM, h_f, NIn);
            gemm_h<0><<<g2, 256, GEMM_SMEM>>>(h_f, w_f + wo + 65536,
                pb2 + (size_t)t * C_DIM, p_f, NIn);
            // memset directly before edge kernel keeps agg resident in L2 for the atomics
            cudaMemsetAsync(aggb, 0, (size_t)NIn * C_DIM * sizeof(float));
            edge_msg_kernel<<<(nE0 * 32 + 255) / 256, 256>>>(xu_f, p_f, ei_ui,
                msg_g + (size_t)t * C_DIM, msg_b + (size_t)t * C_DIM, aggb, nE0);
            norm_agg_f16_kernel<<<(NIn * 64 + 255) / 256, 256>>>(aggb, cnt_i, a_f, NIn);
            gemm_lin<<<g2, 256, GEMM_SMEM>>>(xi_f, a_f, w_f + wo + 131072,
                lin_b + (size_t)t * C_DIM, ni_f, NIn);
        }
        // ---- conv: dst = user, src = item (params [l,1]) ----
        {
            int t = l * 2 + 1;
            size_t wo = (size_t)t * WSTRIDE;
            dim3 g2((NUn + 127) / 128, 2);
            gemm_h<1><<<g2, 256, GEMM_SMEM>>>(xu_f, w_f + wo,
                pb1 + (size_t)t * C_DIM, h_f, NUn);
            gemm_h<0><<<g2, 256, GEMM_SMEM>>>(h_f, w_f + wo + 65536,
                pb2 + (size_t)t * C_DIM, p_f, NUn);
            cudaMemsetAsync(aggb, 0, (size_t)NUn * C_DIM * sizeof(float));
            edge_msg_kernel<<<(nE1 * 32 + 255) / 256, 256>>>(xi_f, p_f, ei_iu,
                msg_g + (size_t)t * C_DIM, msg_b + (size_t)t * C_DIM, aggb, nE1);
            norm_agg_f16_kernel<<<(NUn * 64 + 255) / 256, 256>>>(aggb, cnt_u, a_f, NUn);
            gemm_lin<<<g2, 256, GEMM_SMEM>>>(xu_f, a_f, w_f + wo + 131072,
                lin_b + (size_t)t * C_DIM, nu_f, NUn);
        }
        // ---- node LN + relu ----
        node_ln_relu_kernel<<<(NUn * 32 + 255) / 256, 256>>>(nu_f,
            node_g + (size_t)(l * 2 + 0) * C_DIM, node_b + (size_t)(l * 2 + 0) * C_DIM,
            last ? out_f : (float*)0, last ? (f16*)0 : xu_f, NUn);
        node_ln_relu_kernel<<<(NIn * 32 + 255) / 256, 256>>>(ni_f,
            node_g + (size_t)(l * 2 + 1) * C_DIM, node_b + (size_t)(l * 2 + 1) * C_DIM,
            last ? (out_f + (size_t)NUn * C_DIM) : (float*)0, last ? (f16*)0 : xi_f, NIn);
    }
    (void)n_in; (void)out_size;
}